// round 4
// baseline (speedup 1.0000x reference)
#include <cuda_runtime.h>
#include <cstdint>

typedef unsigned long long ull;

#define N_NODES 16384
#define N_EDGES 524288
#define N_LBL   131072

// ---- output layout (flattened float32 concat in reference-return order) ----
#define O_SAGE1 0ull
#define L_SAGE1 (16384ull*128ull)
#define O_Z     (O_SAGE1 + L_SAGE1)
#define L_Z     (16384ull*64ull)
#define O_DMUL  (O_Z + L_Z)
#define L_DMUL  (131072ull*64ull)
#define O_DSUM  (O_DMUL + L_DMUL)
#define L_DSUM  (131072ull)
#define O_PADJ  (O_DSUM + L_DSUM)
#define L_PADJ  (16384ull*16384ull)
#define O_MASK  (O_PADJ + L_PADJ)

// ---- scratch (device globals; no allocation allowed) ----
__device__ __align__(16) float g_agg1[N_NODES * 128];
__device__ __align__(16) float g_agg2[N_NODES * 128];
__device__ __align__(16) float g_deg[N_NODES];
__device__ __align__(16) float g_invdeg[N_NODES];

// ============================================================
// zero scratch: 2 * 16384*128 + 16384 floats = 1,052,672 float4
// ============================================================
__global__ void k_zero() {
    unsigned i = blockIdx.x * 256u + threadIdx.x;
    float4 zv = make_float4(0.f, 0.f, 0.f, 0.f);
    if (i < 524288u) {
        reinterpret_cast<float4*>(g_agg1)[i] = zv;
    } else if (i < 1048576u) {
        reinterpret_cast<float4*>(g_agg2)[i - 524288u] = zv;
    } else if (i < 1052672u) {
        reinterpret_cast<float4*>(g_deg)[i - 1048576u] = zv;
    }
}

// ============================================================
// scatter-add: one warp per edge, 4 channels (float4) per lane
// ============================================================
__device__ __forceinline__ void scatter_body(const float* __restrict__ feat,
                                             const int* __restrict__ src,
                                             const int* __restrict__ dst,
                                             float* agg, float* deg, int addDeg) {
    unsigned t = blockIdx.x * 256u + threadIdx.x;
    unsigned e = t >> 5, lane = t & 31u;
    if (e >= N_EDGES) return;
    int s = src[e], d = dst[e];
    float4 v = reinterpret_cast<const float4*>(feat + (size_t)s * 128)[lane];
    float* p = agg + (size_t)d * 128 + lane * 4;
    atomicAdd(p + 0, v.x);
    atomicAdd(p + 1, v.y);
    atomicAdd(p + 2, v.z);
    atomicAdd(p + 3, v.w);
    if (addDeg && lane == 0) atomicAdd(deg + d, 1.0f);
}

__global__ void k_scatter1(const float* __restrict__ x,
                           const int* __restrict__ src, const int* __restrict__ dst) {
    scatter_body(x, src, dst, g_agg1, g_deg, 1);
}
__global__ void k_scatter2(const float* __restrict__ sage1,
                           const int* __restrict__ src, const int* __restrict__ dst) {
    scatter_body(sage1, src, dst, g_agg2, g_deg, 0);
}

__global__ void k_invdeg() {
    int i = blockIdx.x * 256 + threadIdx.x;
    if (i < N_NODES) g_invdeg[i] = 1.0f / fmaxf(g_deg[i], 1.0f);
}

// ============================================================
// Layer 1: sage1 = relu( mean1 @ W_l1 + b_l1 + x @ W_r1 )
// Single GEMM view: Y[n, 0:128]=mean1, Y[n,128:256]=x ;  Wcat[256][128]
// Block: 32 rows x 128 cols, 256 threads, thread tile 2x8.
// ============================================================
#define YS_STRIDE 68
__global__ void __launch_bounds__(256) k_gemm1(const float* __restrict__ x,
                                               const float* __restrict__ Wl,
                                               const float* __restrict__ Wr,
                                               const float* __restrict__ bias,
                                               float* __restrict__ out) {
    __shared__ float Ws[64 * 128];
    __shared__ float Ys[32 * YS_STRIDE];
    const int t = threadIdx.x;
    const int row0 = blockIdx.x * 32;
    const int tr = t >> 4, tc = t & 15;

    float acc[2][8];
#pragma unroll
    for (int jj = 0; jj < 8; jj++) {
        float bv = bias[tc * 8 + jj];
        acc[0][jj] = bv; acc[1][jj] = bv;
    }

    for (int c = 0; c < 4; c++) {
        // W chunk: rows g = c*64 + l (l in 0..63), 128 cols
        for (int i = t; i < 2048; i += 256) {
            int l = i >> 5, q = i & 31;
            int g = c * 64 + l;
            float4 v = (g < 128)
                ? reinterpret_cast<const float4*>(Wl + (size_t)g * 128)[q]
                : reinterpret_cast<const float4*>(Wr + (size_t)(g - 128) * 128)[q];
            reinterpret_cast<float4*>(Ws + l * 128)[q] = v;
        }
        // Y chunk: 32 rows x 64 k
        for (int i = t; i < 512; i += 256) {
            int r = i >> 4, q = i & 15;
            int n = row0 + r;
            float4 v;
            if (c < 2) {
                v = reinterpret_cast<const float4*>(g_agg1 + (size_t)n * 128 + c * 64)[q];
                float s = g_invdeg[n];
                v.x *= s; v.y *= s; v.z *= s; v.w *= s;
            } else {
                v = reinterpret_cast<const float4*>(x + (size_t)n * 128 + (c - 2) * 64)[q];
            }
            reinterpret_cast<float4*>(Ys + r * YS_STRIDE)[q] = v;
        }
        __syncthreads();
#pragma unroll 8
        for (int k = 0; k < 64; k++) {
            float a0 = Ys[(2 * tr) * YS_STRIDE + k];
            float a1 = Ys[(2 * tr + 1) * YS_STRIDE + k];
            float w[8];
            *reinterpret_cast<float4*>(w)     = *reinterpret_cast<const float4*>(Ws + k * 128 + tc * 8);
            *reinterpret_cast<float4*>(w + 4) = *reinterpret_cast<const float4*>(Ws + k * 128 + tc * 8 + 4);
#pragma unroll
            for (int jj = 0; jj < 8; jj++) {
                acc[0][jj] = fmaf(a0, w[jj], acc[0][jj]);
                acc[1][jj] = fmaf(a1, w[jj], acc[1][jj]);
            }
        }
        __syncthreads();
    }
#pragma unroll
    for (int ii = 0; ii < 2; ii++) {
        size_t off = (size_t)(row0 + 2 * tr + ii) * 128 + tc * 8;
        float4 v0 = make_float4(fmaxf(acc[ii][0], 0.f), fmaxf(acc[ii][1], 0.f),
                                fmaxf(acc[ii][2], 0.f), fmaxf(acc[ii][3], 0.f));
        float4 v1 = make_float4(fmaxf(acc[ii][4], 0.f), fmaxf(acc[ii][5], 0.f),
                                fmaxf(acc[ii][6], 0.f), fmaxf(acc[ii][7], 0.f));
        *reinterpret_cast<float4*>(out + off)     = v0;
        *reinterpret_cast<float4*>(out + off + 4) = v1;
    }
}

// ============================================================
// Layer 2: z = mean2 @ W_l2 + b_l2 + sage1 @ W_r2   (K=256, N=64)
// Block: 32 rows x 64 cols, 256 threads, thread tile 1x8.
// ============================================================
__global__ void __launch_bounds__(256) k_gemm2(const float* __restrict__ sage1,
                                               const float* __restrict__ Wl,
                                               const float* __restrict__ Wr,
                                               const float* __restrict__ bias,
                                               float* __restrict__ out) {
    __shared__ float Ws[64 * 64];
    __shared__ float Ys[32 * YS_STRIDE];
    const int t = threadIdx.x;
    const int row0 = blockIdx.x * 32;
    const int tr = t >> 3, tc = t & 7;

    float acc[8];
#pragma unroll
    for (int jj = 0; jj < 8; jj++) acc[jj] = bias[tc * 8 + jj];

    for (int c = 0; c < 4; c++) {
        for (int i = t; i < 1024; i += 256) {
            int l = i >> 4, q = i & 15;
            int g = c * 64 + l;
            float4 v = (g < 128)
                ? reinterpret_cast<const float4*>(Wl + (size_t)g * 64)[q]
                : reinterpret_cast<const float4*>(Wr + (size_t)(g - 128) * 64)[q];
            reinterpret_cast<float4*>(Ws + l * 64)[q] = v;
        }
        for (int i = t; i < 512; i += 256) {
            int r = i >> 4, q = i & 15;
            int n = row0 + r;
            float4 v;
            if (c < 2) {
                v = reinterpret_cast<const float4*>(g_agg2 + (size_t)n * 128 + c * 64)[q];
                float s = g_invdeg[n];
                v.x *= s; v.y *= s; v.z *= s; v.w *= s;
            } else {
                v = reinterpret_cast<const float4*>(sage1 + (size_t)n * 128 + (c - 2) * 64)[q];
            }
            reinterpret_cast<float4*>(Ys + r * YS_STRIDE)[q] = v;
        }
        __syncthreads();
#pragma unroll 8
        for (int k = 0; k < 64; k++) {
            float a = Ys[tr * YS_STRIDE + k];
            float w[8];
            *reinterpret_cast<float4*>(w)     = *reinterpret_cast<const float4*>(Ws + k * 64 + tc * 8);
            *reinterpret_cast<float4*>(w + 4) = *reinterpret_cast<const float4*>(Ws + k * 64 + tc * 8 + 4);
#pragma unroll
            for (int jj = 0; jj < 8; jj++) acc[jj] = fmaf(a, w[jj], acc[jj]);
        }
        __syncthreads();
    }
    size_t off = (size_t)(row0 + tr) * 64 + tc * 8;
    float4 v0 = make_float4(acc[0], acc[1], acc[2], acc[3]);
    float4 v1 = make_float4(acc[4], acc[5], acc[6], acc[7]);
    *reinterpret_cast<float4*>(out + off)     = v0;
    *reinterpret_cast<float4*>(out + off + 4) = v1;
}

// ============================================================
// decode: one warp per label edge; 2 channels (float2) per lane
// ============================================================
__global__ void k_decode(const float* __restrict__ z, const int* __restrict__ elbl,
                         float* __restrict__ dmul, float* __restrict__ dsum) {
    unsigned t = blockIdx.x * 256u + threadIdx.x;
    unsigned e = t >> 5, lane = t & 31u;
    if (e >= N_LBL) return;
    int a = elbl[e], b = elbl[N_LBL + e];
    float2 za = reinterpret_cast<const float2*>(z + (size_t)a * 64)[lane];
    float2 zb = reinterpret_cast<const float2*>(z + (size_t)b * 64)[lane];
    float2 m = make_float2(za.x * zb.x, za.y * zb.y);
    reinterpret_cast<float2*>(dmul + (size_t)e * 64)[lane] = m;
    float s = m.x + m.y;
#pragma unroll
    for (int o = 16; o > 0; o >>= 1) s += __shfl_xor_sync(0xffffffffu, s, o);
    if (lane == 0) dsum[e] = s;
}

// ============================================================
// big GEMM: prob_adj = z @ z^T (16384 x 16384, K=64) + mask (>0)
// Block tile 128x128, 256 threads, thread tile 8x8 via fma.rn.f32x2.
// A tile stored k-major DUPLICATED pairs (a,a); B tile k-major.
// smem: Adup 64x256 fp32 (64KB) + Bs 64x128 fp32 (32KB) = 96KB dynamic.
// ============================================================
__device__ __forceinline__ void fma2(ull& acc, ull a, ull b) {
    asm("fma.rn.f32x2 %0, %1, %2, %0;" : "+l"(acc) : "l"(a), "l"(b));
}

__global__ void __launch_bounds__(256, 2) k_bigmm(const float* __restrict__ z,
                                                  float* __restrict__ padj,
                                                  float* __restrict__ maskp) {
    extern __shared__ float sm[];
    float* Adup = sm;             // [k][2*i] : 64 x 256
    float* Bs   = sm + 64 * 256;  // [k][j]   : 64 x 128
    const int t  = threadIdx.x;
    const int bi = blockIdx.y, bj = blockIdx.x;

    // Load A rows (bi*128 .. +127), duplicate each value into an f32x2 pair.
    for (int i = t; i < 2048; i += 256) {
        int r = i & 127;
        int q = (i >> 7) & 15;
        float4 v = reinterpret_cast<const float4*>(z + (size_t)(bi * 128 + r) * 64)[q];
        float2* ad = reinterpret_cast<float2*>(Adup);
        int k0 = q * 4;
        ad[(k0 + 0) * 128 + r] = make_float2(v.x, v.x);
        ad[(k0 + 1) * 128 + r] = make_float2(v.y, v.y);
        ad[(k0 + 2) * 128 + r] = make_float2(v.z, v.z);
        ad[(k0 + 3) * 128 + r] = make_float2(v.w, v.w);
    }
    // Load B rows (bj*128 .. +127) transposed to [k][j].
    for (int i = t; i < 2048; i += 256) {
        int r = i & 127;
        int q = (i >> 7) & 15;
        float4 v = reinterpret_cast<const float4*>(z + (size_t)(bj * 128 + r) * 64)[q];
        int k0 = q * 4;
        Bs[(k0 + 0) * 128 + r] = v.x;
        Bs[(k0 + 1) * 128 + r] = v.y;
        Bs[(k0 + 2) * 128 + r] = v.z;
        Bs[(k0 + 3) * 128 + r] = v.w;
    }
    __syncthreads();

    const int ti = t >> 4, tj = t & 15;
    ull acc[8][4];
#pragma unroll
    for (int ii = 0; ii < 8; ii++)
#pragma unroll
        for (int jj = 0; jj < 4; jj++) acc[ii][jj] = 0ull;

    // Adup row = 256 floats = 64 ulonglong2 ; thread offset = ti*16 floats = ti*4 u64x2
    const ulonglong2* Ab = reinterpret_cast<const ulonglong2*>(Adup) + ti * 4;
    // Bs row = 128 floats = 32 ulonglong2 ; thread offset = tj*8 floats = tj*2 u64x2
    const ulonglong2* Bb = reinterpret_cast<const ulonglong2*>(Bs) + tj * 2;

#pragma unroll 4
    for (int k = 0; k < 64; k++) {
        ulonglong2 a01 = Ab[k * 64 + 0];
        ulonglong2 a23 = Ab[k * 64 + 1];
        ulonglong2 a45 = Ab[k * 64 + 2];
        ulonglong2 a67 = Ab[k * 64 + 3];
        ulonglong2 b01 = Bb[k * 32 + 0];
        ulonglong2 b23 = Bb[k * 32 + 1];
        ull a[8] = {a01.x, a01.y, a23.x, a23.y, a45.x, a45.y, a67.x, a67.y};
        ull b[4] = {b01.x, b01.y, b23.x, b23.y};
#pragma unroll
        for (int ii = 0; ii < 8; ii++)
#pragma unroll
            for (int jj = 0; jj < 4; jj++) fma2(acc[ii][jj], a[ii], b[jj]);
    }

    const size_t i0 = (size_t)bi * 128 + (size_t)ti * 8;
    const size_t j0 = (size_t)bj * 128 + (size_t)tj * 8;
#pragma unroll
    for (int ii = 0; ii < 8; ii++) {
        size_t off = (i0 + ii) * 16384ull + j0;
        float2 f0 = *reinterpret_cast<float2*>(&acc[ii][0]);
        float2 f1 = *reinterpret_cast<float2*>(&acc[ii][1]);
        float2 f2 = *reinterpret_cast<float2*>(&acc[ii][2]);
        float2 f3 = *reinterpret_cast<float2*>(&acc[ii][3]);
        float4 v0 = make_float4(f0.x, f0.y, f1.x, f1.y);
        float4 v1 = make_float4(f2.x, f2.y, f3.x, f3.y);
        __stcs(reinterpret_cast<float4*>(padj + off),     v0);
        __stcs(reinterpret_cast<float4*>(padj + off + 4), v1);
        float4 m0 = make_float4(v0.x > 0.f ? 1.f : 0.f, v0.y > 0.f ? 1.f : 0.f,
                                v0.z > 0.f ? 1.f : 0.f, v0.w > 0.f ? 1.f : 0.f);
        float4 m1 = make_float4(v1.x > 0.f ? 1.f : 0.f, v1.y > 0.f ? 1.f : 0.f,
                                v1.z > 0.f ? 1.f : 0.f, v1.w > 0.f ? 1.f : 0.f);
        __stcs(reinterpret_cast<float4*>(maskp + off),     m0);
        __stcs(reinterpret_cast<float4*>(maskp + off + 4), m1);
    }
}

// ============================================================
extern "C" void kernel_launch(void* const* d_in, const int* in_sizes, int n_in,
                              void* d_out, int out_size) {
    const float* x   = (const float*)d_in[0];
    const int*   ei  = (const int*)d_in[1];
    const int*   elb = (const int*)d_in[2];
    const float* Wl1 = (const float*)d_in[3];
    const float* bl1 = (const float*)d_in[4];
    const float* Wr1 = (const float*)d_in[5];
    const float* Wl2 = (const float*)d_in[6];
    const float* bl2 = (const float*)d_in[7];
    const float* Wr2 = (const float*)d_in[8];

    float* out   = (float*)d_out;
    float* sage1 = out + O_SAGE1;
    float* z     = out + O_Z;
    float* dmul  = out + O_DMUL;
    float* dsum  = out + O_DSUM;
    float* padj  = out + O_PADJ;
    float* maskp = out + O_MASK;

    (void)cudaFuncSetAttribute(k_bigmm, cudaFuncAttributeMaxDynamicSharedMemorySize, 98304);

    k_zero<<<4112, 256>>>();
    k_scatter1<<<65536, 256>>>(x, ei, ei + N_EDGES);
    k_invdeg<<<64, 256>>>();
    k_gemm1<<<512, 256>>>(x, Wl1, Wr1, bl1, sage1);
    k_scatter2<<<65536, 256>>>(sage1, ei, ei + N_EDGES);
    k_gemm2<<<512, 256>>>(sage1, Wl2, Wr2, bl2, z);
    k_decode<<<16384, 256>>>(z, elb, dmul, dsum);
    k_bigmm<<<dim3(128, 128), 256, 98304>>>(z, padj, maskp);
}

// round 9
// speedup vs baseline: 1.2967x; 1.2967x over previous
#include <cuda_runtime.h>
#include <cuda_bf16.h>
#include <cstdint>

typedef unsigned long long ull;

#define N_NODES 16384
#define N_EDGES 524288
#define N_LBL   131072

// ---- output layout (flattened float32 concat in reference-return order) ----
#define O_SAGE1 0ull
#define L_SAGE1 (16384ull*128ull)
#define O_Z     (O_SAGE1 + L_SAGE1)
#define L_Z     (16384ull*64ull)
#define O_DMUL  (O_Z + L_Z)
#define L_DMUL  (131072ull*64ull)
#define O_DSUM  (O_DMUL + L_DMUL)
#define L_DSUM  (131072ull)
#define O_PADJ  (O_DSUM + L_DSUM)
#define L_PADJ  (16384ull*16384ull)
#define O_MASK  (O_PADJ + L_PADJ)

// ---- scratch (device globals; no allocation allowed) ----
__device__ __align__(16) float g_agg1[N_NODES * 128];
__device__ __align__(16) float g_agg2[N_NODES * 128];
__device__ __align__(16) float g_deg[N_NODES];
__device__ __align__(16) float g_invdeg[N_NODES];
// exact 3-way bf16 split of z: z = h + m + l
__device__ __align__(16) __nv_bfloat16 g_zh[N_NODES * 64];
__device__ __align__(16) __nv_bfloat16 g_zm[N_NODES * 64];
__device__ __align__(16) __nv_bfloat16 g_zl[N_NODES * 64];

// ============================================================
// zero scratch
// ============================================================
__global__ void k_zero() {
    unsigned i = blockIdx.x * 256u + threadIdx.x;
    float4 zv = make_float4(0.f, 0.f, 0.f, 0.f);
    if (i < 524288u) {
        reinterpret_cast<float4*>(g_agg1)[i] = zv;
    } else if (i < 1048576u) {
        reinterpret_cast<float4*>(g_agg2)[i - 524288u] = zv;
    } else if (i < 1052672u) {
        reinterpret_cast<float4*>(g_deg)[i - 1048576u] = zv;
    }
}

// ============================================================
// scatter-add: one warp per edge, 4 channels (float4) per lane
// ============================================================
__device__ __forceinline__ void scatter_body(const float* __restrict__ feat,
                                             const int* __restrict__ src,
                                             const int* __restrict__ dst,
                                             float* agg, float* deg, int addDeg) {
    unsigned t = blockIdx.x * 256u + threadIdx.x;
    unsigned e = t >> 5, lane = t & 31u;
    if (e >= N_EDGES) return;
    int s = src[e], d = dst[e];
    float4 v = reinterpret_cast<const float4*>(feat + (size_t)s * 128)[lane];
    float* p = agg + (size_t)d * 128 + lane * 4;
    atomicAdd(p + 0, v.x);
    atomicAdd(p + 1, v.y);
    atomicAdd(p + 2, v.z);
    atomicAdd(p + 3, v.w);
    if (addDeg && lane == 0) atomicAdd(deg + d, 1.0f);
}

__global__ void k_scatter1(const float* __restrict__ x,
                           const int* __restrict__ src, const int* __restrict__ dst) {
    scatter_body(x, src, dst, g_agg1, g_deg, 1);
}
__global__ void k_scatter2(const float* __restrict__ sage1,
                           const int* __restrict__ src, const int* __restrict__ dst) {
    scatter_body(sage1, src, dst, g_agg2, g_deg, 0);
}

__global__ void k_invdeg() {
    int i = blockIdx.x * 256 + threadIdx.x;
    if (i < N_NODES) g_invdeg[i] = 1.0f / fmaxf(g_deg[i], 1.0f);
}

// ============================================================
// Layer 1: sage1 = relu( mean1 @ W_l1 + b_l1 + x @ W_r1 )
// ============================================================
#define YS_STRIDE 68
__global__ void __launch_bounds__(256) k_gemm1(const float* __restrict__ x,
                                               const float* __restrict__ Wl,
                                               const float* __restrict__ Wr,
                                               const float* __restrict__ bias,
                                               float* __restrict__ out) {
    __shared__ float Ws[64 * 128];
    __shared__ float Ys[32 * YS_STRIDE];
    const int t = threadIdx.x;
    const int row0 = blockIdx.x * 32;
    const int tr = t >> 4, tc = t & 15;

    float acc[2][8];
#pragma unroll
    for (int jj = 0; jj < 8; jj++) {
        float bv = bias[tc * 8 + jj];
        acc[0][jj] = bv; acc[1][jj] = bv;
    }

    for (int c = 0; c < 4; c++) {
        for (int i = t; i < 2048; i += 256) {
            int l = i >> 5, q = i & 31;
            int g = c * 64 + l;
            float4 v = (g < 128)
                ? reinterpret_cast<const float4*>(Wl + (size_t)g * 128)[q]
                : reinterpret_cast<const float4*>(Wr + (size_t)(g - 128) * 128)[q];
            reinterpret_cast<float4*>(Ws + l * 128)[q] = v;
        }
        for (int i = t; i < 512; i += 256) {
            int r = i >> 4, q = i & 15;
            int n = row0 + r;
            float4 v;
            if (c < 2) {
                v = reinterpret_cast<const float4*>(g_agg1 + (size_t)n * 128 + c * 64)[q];
                float s = g_invdeg[n];
                v.x *= s; v.y *= s; v.z *= s; v.w *= s;
            } else {
                v = reinterpret_cast<const float4*>(x + (size_t)n * 128 + (c - 2) * 64)[q];
            }
            reinterpret_cast<float4*>(Ys + r * YS_STRIDE)[q] = v;
        }
        __syncthreads();
#pragma unroll 8
        for (int k = 0; k < 64; k++) {
            float a0 = Ys[(2 * tr) * YS_STRIDE + k];
            float a1 = Ys[(2 * tr + 1) * YS_STRIDE + k];
            float w[8];
            *reinterpret_cast<float4*>(w)     = *reinterpret_cast<const float4*>(Ws + k * 128 + tc * 8);
            *reinterpret_cast<float4*>(w + 4) = *reinterpret_cast<const float4*>(Ws + k * 128 + tc * 8 + 4);
#pragma unroll
            for (int jj = 0; jj < 8; jj++) {
                acc[0][jj] = fmaf(a0, w[jj], acc[0][jj]);
                acc[1][jj] = fmaf(a1, w[jj], acc[1][jj]);
            }
        }
        __syncthreads();
    }
#pragma unroll
    for (int ii = 0; ii < 2; ii++) {
        size_t off = (size_t)(row0 + 2 * tr + ii) * 128 + tc * 8;
        float4 v0 = make_float4(fmaxf(acc[ii][0], 0.f), fmaxf(acc[ii][1], 0.f),
                                fmaxf(acc[ii][2], 0.f), fmaxf(acc[ii][3], 0.f));
        float4 v1 = make_float4(fmaxf(acc[ii][4], 0.f), fmaxf(acc[ii][5], 0.f),
                                fmaxf(acc[ii][6], 0.f), fmaxf(acc[ii][7], 0.f));
        *reinterpret_cast<float4*>(out + off)     = v0;
        *reinterpret_cast<float4*>(out + off + 4) = v1;
    }
}

// ============================================================
// Layer 2: z = mean2 @ W_l2 + b_l2 + sage1 @ W_r2
// ============================================================
__global__ void __launch_bounds__(256) k_gemm2(const float* __restrict__ sage1,
                                               const float* __restrict__ Wl,
                                               const float* __restrict__ Wr,
                                               const float* __restrict__ bias,
                                               float* __restrict__ out) {
    __shared__ float Ws[64 * 64];
    __shared__ float Ys[32 * YS_STRIDE];
    const int t = threadIdx.x;
    const int row0 = blockIdx.x * 32;
    const int tr = t >> 3, tc = t & 7;

    float acc[8];
#pragma unroll
    for (int jj = 0; jj < 8; jj++) acc[jj] = bias[tc * 8 + jj];

    for (int c = 0; c < 4; c++) {
        for (int i = t; i < 1024; i += 256) {
            int l = i >> 4, q = i & 15;
            int g = c * 64 + l;
            float4 v = (g < 128)
                ? reinterpret_cast<const float4*>(Wl + (size_t)g * 64)[q]
                : reinterpret_cast<const float4*>(Wr + (size_t)(g - 128) * 64)[q];
            reinterpret_cast<float4*>(Ws + l * 64)[q] = v;
        }
        for (int i = t; i < 512; i += 256) {
            int r = i >> 4, q = i & 15;
            int n = row0 + r;
            float4 v;
            if (c < 2) {
                v = reinterpret_cast<const float4*>(g_agg2 + (size_t)n * 128 + c * 64)[q];
                float s = g_invdeg[n];
                v.x *= s; v.y *= s; v.z *= s; v.w *= s;
            } else {
                v = reinterpret_cast<const float4*>(sage1 + (size_t)n * 128 + (c - 2) * 64)[q];
            }
            reinterpret_cast<float4*>(Ys + r * YS_STRIDE)[q] = v;
        }
        __syncthreads();
#pragma unroll 8
        for (int k = 0; k < 64; k++) {
            float a = Ys[tr * YS_STRIDE + k];
            float w[8];
            *reinterpret_cast<float4*>(w)     = *reinterpret_cast<const float4*>(Ws + k * 64 + tc * 8);
            *reinterpret_cast<float4*>(w + 4) = *reinterpret_cast<const float4*>(Ws + k * 64 + tc * 8 + 4);
#pragma unroll
            for (int jj = 0; jj < 8; jj++) acc[jj] = fmaf(a, w[jj], acc[jj]);
        }
        __syncthreads();
    }
    size_t off = (size_t)(row0 + tr) * 64 + tc * 8;
    float4 v0 = make_float4(acc[0], acc[1], acc[2], acc[3]);
    float4 v1 = make_float4(acc[4], acc[5], acc[6], acc[7]);
    *reinterpret_cast<float4*>(out + off)     = v0;
    *reinterpret_cast<float4*>(out + off + 4) = v1;
}

// ============================================================
// decode: one warp per label edge
// ============================================================
__global__ void k_decode(const float* __restrict__ z, const int* __restrict__ elbl,
                         float* __restrict__ dmul, float* __restrict__ dsum) {
    unsigned t = blockIdx.x * 256u + threadIdx.x;
    unsigned e = t >> 5, lane = t & 31u;
    if (e >= N_LBL) return;
    int a = elbl[e], b = elbl[N_LBL + e];
    float2 za = reinterpret_cast<const float2*>(z + (size_t)a * 64)[lane];
    float2 zb = reinterpret_cast<const float2*>(z + (size_t)b * 64)[lane];
    float2 m = make_float2(za.x * zb.x, za.y * zb.y);
    reinterpret_cast<float2*>(dmul + (size_t)e * 64)[lane] = m;
    float s = m.x + m.y;
#pragma unroll
    for (int o = 16; o > 0; o >>= 1) s += __shfl_xor_sync(0xffffffffu, s, o);
    if (lane == 0) dsum[e] = s;
}

// ============================================================
// split z into exact bf16 triple: z = h + m + l
// ============================================================
__global__ void k_split(const float* __restrict__ z) {
    int i = blockIdx.x * 256 + threadIdx.x;   // 1048576 elems, grid 4096
    float v = z[i];
    __nv_bfloat16 h = __float2bfloat16(v);
    float r1 = v - __bfloat162float(h);
    __nv_bfloat16 m = __float2bfloat16(r1);
    float r2 = r1 - __bfloat162float(m);
    __nv_bfloat16 l = __float2bfloat16(r2);
    g_zh[i] = h; g_zm[i] = m; g_zl[i] = l;
}

// ============================================================
// mma.sync helpers (plain PTX, valid on non-'a' sm_103 target)
// ============================================================
__device__ __forceinline__ uint32_t smem_u32(const void* p) {
    uint32_t a;
    asm("{ .reg .u64 t; cvta.to.shared.u64 t, %1; cvt.u32.u64 %0, t; }" : "=r"(a) : "l"(p));
    return a;
}
__device__ __forceinline__ void ldmx4(uint32_t* r, uint32_t addr) {
    asm volatile("ldmatrix.sync.aligned.m8n8.x4.shared.b16 {%0,%1,%2,%3}, [%4];"
                 : "=r"(r[0]), "=r"(r[1]), "=r"(r[2]), "=r"(r[3]) : "r"(addr));
}
__device__ __forceinline__ void mma_bf16(float* d, const uint32_t* a, uint32_t b0, uint32_t b1) {
    asm volatile("mma.sync.aligned.m16n8k16.row.col.f32.bf16.bf16.f32 "
                 "{%0,%1,%2,%3}, {%4,%5,%6,%7}, {%8,%9}, {%0,%1,%2,%3};"
                 : "+f"(d[0]), "+f"(d[1]), "+f"(d[2]), "+f"(d[3])
                 : "r"(a[0]), "r"(a[1]), "r"(a[2]), "r"(a[3]), "r"(b0), "r"(b1));
}

// ============================================================
// big GEMM: prob_adj = z @ z^T via exact bf16 3-split, mma.sync HMMA.
// CTA tile 128x128, 8 warps (4 along M x 2 along N), warp tile 32x64.
// 6 products (hh, hm, mh, mm, hl, lh): dropped terms ~2^-24 rel == fp32 level.
// smem: A tiles 3 x 128rows x 128B + B tiles same = 96KB dynamic, XOR swizzle.
// ============================================================
#define SMEM_MM 98304

__global__ void __launch_bounds__(256) k_bigmm_mma(float* __restrict__ padj,
                                                   float* __restrict__ maskp) {
    extern __shared__ char smem[];
    const uint32_t sA = smem_u32(smem);
    const uint32_t sB = sA + 49152;
    const int tid = threadIdx.x;
    const int wid = tid >> 5, lane = tid & 31;
    const int bi = blockIdx.y, bj = blockIdx.x;

    // ---- fill A tiles: 3 arrays x 128 rows x 8 x 16B chunks ----
    for (int i = tid; i < 3072; i += 256) {
        int arr = i >> 10, rem = i & 1023;
        int r = rem >> 3, c = rem & 7;
        const __nv_bfloat16* src = (arr == 0) ? g_zh : (arr == 1) ? g_zm : g_zl;
        uint4 v = reinterpret_cast<const uint4*>(src + (size_t)(bi * 128 + r) * 64)[c];
        *reinterpret_cast<uint4*>(smem + arr * 16384 + r * 128 + ((c ^ (r & 7)) << 4)) = v;
    }
    // ---- fill B tiles ----
    for (int i = tid; i < 3072; i += 256) {
        int arr = i >> 10, rem = i & 1023;
        int r = rem >> 3, c = rem & 7;
        const __nv_bfloat16* src = (arr == 0) ? g_zh : (arr == 1) ? g_zm : g_zl;
        uint4 v = reinterpret_cast<const uint4*>(src + (size_t)(bj * 128 + r) * 64)[c];
        *reinterpret_cast<uint4*>(smem + 49152 + arr * 16384 + r * 128 + ((c ^ (r & 7)) << 4)) = v;
    }
    __syncthreads();

    const int wm = (wid & 3) * 32;   // warp M offset
    const int wn = (wid >> 2) * 64;  // warp N offset
    const int lm = lane & 15, lh = lane >> 4;

    float acc[2][8][4];
#pragma unroll
    for (int mi = 0; mi < 2; mi++)
#pragma unroll
        for (int jj = 0; jj < 8; jj++)
#pragma unroll
            for (int q = 0; q < 4; q++) acc[mi][jj][q] = 0.f;

    const int PA[6] = {0, 0, 1, 1, 0, 2};
    const int PB[6] = {0, 1, 0, 1, 2, 0};

    for (int ks = 0; ks < 4; ks++) {
        const int ch = ks * 2 + lh;          // 16B k-chunk index (0..7)
#pragma unroll
        for (int p = 0; p < 6; p++) {
            uint32_t af[2][4];
#pragma unroll
            for (int mi = 0; mi < 2; mi++) {
                int r = wm + mi * 16 + lm;
                ldmx4(af[mi], sA + PA[p] * 16384 + r * 128 + ((ch ^ (r & 7)) << 4));
            }
            uint32_t bfr[4][4];
#pragma unroll
            for (int nb = 0; nb < 4; nb++) {
                int r = wn + nb * 16 + lm;
                ldmx4(bfr[nb], sB + PB[p] * 16384 + r * 128 + ((ch ^ (r & 7)) << 4));
            }
#pragma unroll
            for (int mi = 0; mi < 2; mi++)
#pragma unroll
                for (int nb = 0; nb < 4; nb++) {
                    mma_bf16(acc[mi][nb * 2 + 0], af[mi], bfr[nb][0], bfr[nb][2]);
                    mma_bf16(acc[mi][nb * 2 + 1], af[mi], bfr[nb][1], bfr[nb][3]);
                }
        }
    }

    // ---- epilogue: direct float2 stores (full 32B sectors per row segment) ----
    const int rowb = bi * 128 + wm + (lane >> 2);
    const int colb = bj * 128 + wn + (lane & 3) * 2;
#pragma unroll
    for (int mi = 0; mi < 2; mi++) {
#pragma unroll
        for (int jj = 0; jj < 8; jj++) {
            const float* d = acc[mi][jj];
            size_t o0 = (size_t)(rowb + mi * 16) * 16384ull + colb + jj * 8;
            size_t o1 = o0 + 8ull * 16384ull;
            float2 v0 = make_float2(d[0], d[1]);
            float2 v1 = make_float2(d[2], d[3]);
            __stcs(reinterpret_cast<float2*>(padj + o0), v0);
            __stcs(reinterpret_cast<float2*>(padj + o1), v1);
            float2 m0 = make_float2(v0.x > 0.f ? 1.f : 0.f, v0.y > 0.f ? 1.f : 0.f);
            float2 m1 = make_float2(v1.x > 0.f ? 1.f : 0.f, v1.y > 0.f ? 1.f : 0.f);
            __stcs(reinterpret_cast<float2*>(maskp + o0), m0);
            __stcs(reinterpret_cast<float2*>(maskp + o1), m1);
        }
    }
}

// ============================================================
extern "C" void kernel_launch(void* const* d_in, const int* in_sizes, int n_in,
                              void* d_out, int out_size) {
    const float* x   = (const float*)d_in[0];
    const int*   ei  = (const int*)d_in[1];
    const int*   elb = (const int*)d_in[2];
    const float* Wl1 = (const float*)d_in[3];
    const float* bl1 = (const float*)d_in[4];
    const float* Wr1 = (const float*)d_in[5];
    const float* Wl2 = (const float*)d_in[6];
    const float* bl2 = (const float*)d_in[7];
    const float* Wr2 = (const float*)d_in[8];

    float* out   = (float*)d_out;
    float* sage1 = out + O_SAGE1;
    float* z     = out + O_Z;
    float* dmul  = out + O_DMUL;
    float* dsum  = out + O_DSUM;
    float* padj  = out + O_PADJ;
    float* maskp = out + O_MASK;

    (void)cudaFuncSetAttribute(k_bigmm_mma, cudaFuncAttributeMaxDynamicSharedMemorySize, SMEM_MM);

    k_zero<<<4112, 256>>>();
    k_scatter1<<<65536, 256>>>(x, ei, ei + N_EDGES);
    k_invdeg<<<64, 256>>>();
    k_gemm1<<<512, 256>>>(x, Wl1, Wr1, bl1, sage1);
    k_scatter2<<<65536, 256>>>(sage1, ei, ei + N_EDGES);
    k_gemm2<<<512, 256>>>(sage1, Wl2, Wr2, bl2, z);
    k_split<<<4096, 256>>>(z);
    k_decode<<<16384, 256>>>(z, elb, dmul, dsum);
    k_bigmm_mma<<<dim3(128, 128), 256, SMEM_MM>>>(padj, maskp);
}

// round 10
// speedup vs baseline: 1.5489x; 1.1945x over previous
#include <cuda_runtime.h>
#include <cuda_bf16.h>
#include <cstdint>

typedef unsigned long long ull;

#define N_NODES 16384
#define N_EDGES 524288
#define N_LBL   131072

// ---- output layout (flattened float32 concat in reference-return order) ----
#define O_SAGE1 0ull
#define L_SAGE1 (16384ull*128ull)
#define O_Z     (O_SAGE1 + L_SAGE1)
#define L_Z     (16384ull*64ull)
#define O_DMUL  (O_Z + L_Z)
#define L_DMUL  (131072ull*64ull)
#define O_DSUM  (O_DMUL + L_DMUL)
#define L_DSUM  (131072ull)
#define O_PADJ  (O_DSUM + L_DSUM)
#define L_PADJ  (16384ull*16384ull)
#define O_MASK  (O_PADJ + L_PADJ)

// ---- scratch (device globals; no allocation allowed) ----
__device__ __align__(16) float g_agg1[N_NODES * 128];
__device__ __align__(16) float g_agg2[N_NODES * 128];
__device__ __align__(16) float g_deg[N_NODES];
__device__ __align__(16) float g_invdeg[N_NODES];
// exact 3-way bf16 split of z: z = h + m + l
__device__ __align__(16) __nv_bfloat16 g_zh[N_NODES * 64];
__device__ __align__(16) __nv_bfloat16 g_zm[N_NODES * 64];
__device__ __align__(16) __nv_bfloat16 g_zl[N_NODES * 64];

// ============================================================
// zero scratch
// ============================================================
__global__ void k_zero() {
    unsigned i = blockIdx.x * 256u + threadIdx.x;
    float4 zv = make_float4(0.f, 0.f, 0.f, 0.f);
    if (i < 524288u) {
        reinterpret_cast<float4*>(g_agg1)[i] = zv;
    } else if (i < 1048576u) {
        reinterpret_cast<float4*>(g_agg2)[i - 524288u] = zv;
    } else if (i < 1052672u) {
        reinterpret_cast<float4*>(g_deg)[i - 1048576u] = zv;
    }
}

// ============================================================
// scatter-add: one warp per edge, float4 vector atomics (sm_90+)
// ============================================================
__device__ __forceinline__ void scatter_body(const float* __restrict__ feat,
                                             const int* __restrict__ src,
                                             const int* __restrict__ dst,
                                             float* agg, float* deg, int addDeg) {
    unsigned t = blockIdx.x * 256u + threadIdx.x;
    unsigned e = t >> 5, lane = t & 31u;
    if (e >= N_EDGES) return;
    int s = src[e], d = dst[e];
    float4 v = reinterpret_cast<const float4*>(feat + (size_t)s * 128)[lane];
    atomicAdd(reinterpret_cast<float4*>(agg + (size_t)d * 128 + lane * 4), v);
    if (addDeg && lane == 0) atomicAdd(deg + d, 1.0f);
}

__global__ void k_scatter1(const float* __restrict__ x,
                           const int* __restrict__ src, const int* __restrict__ dst) {
    scatter_body(x, src, dst, g_agg1, g_deg, 1);
}
__global__ void k_scatter2(const float* __restrict__ sage1,
                           const int* __restrict__ src, const int* __restrict__ dst) {
    scatter_body(sage1, src, dst, g_agg2, g_deg, 0);
}

__global__ void k_invdeg() {
    int i = blockIdx.x * 256 + threadIdx.x;
    if (i < N_NODES) g_invdeg[i] = 1.0f / fmaxf(g_deg[i], 1.0f);
}

// ============================================================
// Layer 1: sage1 = relu( mean1 @ W_l1 + b_l1 + x @ W_r1 )
// Block 64 rows x 128 cols, 256 threads, thread tile 4x8.
// ============================================================
#define YS_STRIDE 68
__global__ void __launch_bounds__(256) k_gemm1(const float* __restrict__ x,
                                               const float* __restrict__ Wl,
                                               const float* __restrict__ Wr,
                                               const float* __restrict__ bias,
                                               float* __restrict__ out) {
    __shared__ float Ws[64 * 128];
    __shared__ float Ys[64 * YS_STRIDE];
    const int t = threadIdx.x;
    const int row0 = blockIdx.x * 64;
    const int tr = t >> 4, tc = t & 15;

    float acc[4][8];
#pragma unroll
    for (int jj = 0; jj < 8; jj++) {
        float bv = bias[tc * 8 + jj];
#pragma unroll
        for (int ii = 0; ii < 4; ii++) acc[ii][jj] = bv;
    }

    for (int c = 0; c < 4; c++) {
        for (int i = t; i < 2048; i += 256) {
            int l = i >> 5, q = i & 31;
            int g = c * 64 + l;
            float4 v = (g < 128)
                ? reinterpret_cast<const float4*>(Wl + (size_t)g * 128)[q]
                : reinterpret_cast<const float4*>(Wr + (size_t)(g - 128) * 128)[q];
            reinterpret_cast<float4*>(Ws + l * 128)[q] = v;
        }
        for (int i = t; i < 1024; i += 256) {
            int r = i >> 4, q = i & 15;
            int n = row0 + r;
            float4 v;
            if (c < 2) {
                v = reinterpret_cast<const float4*>(g_agg1 + (size_t)n * 128 + c * 64)[q];
                float s = g_invdeg[n];
                v.x *= s; v.y *= s; v.z *= s; v.w *= s;
            } else {
                v = reinterpret_cast<const float4*>(x + (size_t)n * 128 + (c - 2) * 64)[q];
            }
            reinterpret_cast<float4*>(Ys + r * YS_STRIDE)[q] = v;
        }
        __syncthreads();
#pragma unroll 4
        for (int k = 0; k < 64; k++) {
            float a[4];
#pragma unroll
            for (int ii = 0; ii < 4; ii++) a[ii] = Ys[(4 * tr + ii) * YS_STRIDE + k];
            float w[8];
            *reinterpret_cast<float4*>(w)     = *reinterpret_cast<const float4*>(Ws + k * 128 + tc * 8);
            *reinterpret_cast<float4*>(w + 4) = *reinterpret_cast<const float4*>(Ws + k * 128 + tc * 8 + 4);
#pragma unroll
            for (int ii = 0; ii < 4; ii++)
#pragma unroll
                for (int jj = 0; jj < 8; jj++) acc[ii][jj] = fmaf(a[ii], w[jj], acc[ii][jj]);
        }
        __syncthreads();
    }
#pragma unroll
    for (int ii = 0; ii < 4; ii++) {
        size_t off = (size_t)(row0 + 4 * tr + ii) * 128 + tc * 8;
        float4 v0 = make_float4(fmaxf(acc[ii][0], 0.f), fmaxf(acc[ii][1], 0.f),
                                fmaxf(acc[ii][2], 0.f), fmaxf(acc[ii][3], 0.f));
        float4 v1 = make_float4(fmaxf(acc[ii][4], 0.f), fmaxf(acc[ii][5], 0.f),
                                fmaxf(acc[ii][6], 0.f), fmaxf(acc[ii][7], 0.f));
        *reinterpret_cast<float4*>(out + off)     = v0;
        *reinterpret_cast<float4*>(out + off + 4) = v1;
    }
}

// ============================================================
// Layer 2: z = mean2 @ W_l2 + b_l2 + sage1 @ W_r2
// ============================================================
__global__ void __launch_bounds__(256) k_gemm2(const float* __restrict__ sage1,
                                               const float* __restrict__ Wl,
                                               const float* __restrict__ Wr,
                                               const float* __restrict__ bias,
                                               float* __restrict__ out) {
    __shared__ float Ws[64 * 64];
    __shared__ float Ys[32 * YS_STRIDE];
    const int t = threadIdx.x;
    const int row0 = blockIdx.x * 32;
    const int tr = t >> 3, tc = t & 7;

    float acc[8];
#pragma unroll
    for (int jj = 0; jj < 8; jj++) acc[jj] = bias[tc * 8 + jj];

    for (int c = 0; c < 4; c++) {
        for (int i = t; i < 1024; i += 256) {
            int l = i >> 4, q = i & 15;
            int g = c * 64 + l;
            float4 v = (g < 128)
                ? reinterpret_cast<const float4*>(Wl + (size_t)g * 64)[q]
                : reinterpret_cast<const float4*>(Wr + (size_t)(g - 128) * 64)[q];
            reinterpret_cast<float4*>(Ws + l * 64)[q] = v;
        }
        for (int i = t; i < 512; i += 256) {
            int r = i >> 4, q = i & 15;
            int n = row0 + r;
            float4 v;
            if (c < 2) {
                v = reinterpret_cast<const float4*>(g_agg2 + (size_t)n * 128 + c * 64)[q];
                float s = g_invdeg[n];
                v.x *= s; v.y *= s; v.z *= s; v.w *= s;
            } else {
                v = reinterpret_cast<const float4*>(sage1 + (size_t)n * 128 + (c - 2) * 64)[q];
            }
            reinterpret_cast<float4*>(Ys + r * YS_STRIDE)[q] = v;
        }
        __syncthreads();
#pragma unroll 8
        for (int k = 0; k < 64; k++) {
            float a = Ys[tr * YS_STRIDE + k];
            float w[8];
            *reinterpret_cast<float4*>(w)     = *reinterpret_cast<const float4*>(Ws + k * 64 + tc * 8);
            *reinterpret_cast<float4*>(w + 4) = *reinterpret_cast<const float4*>(Ws + k * 64 + tc * 8 + 4);
#pragma unroll
            for (int jj = 0; jj < 8; jj++) acc[jj] = fmaf(a, w[jj], acc[jj]);
        }
        __syncthreads();
    }
    size_t off = (size_t)(row0 + tr) * 64 + tc * 8;
    float4 v0 = make_float4(acc[0], acc[1], acc[2], acc[3]);
    float4 v1 = make_float4(acc[4], acc[5], acc[6], acc[7]);
    *reinterpret_cast<float4*>(out + off)     = v0;
    *reinterpret_cast<float4*>(out + off + 4) = v1;
}

// ============================================================
// decode: one warp per label edge
// ============================================================
__global__ void k_decode(const float* __restrict__ z, const int* __restrict__ elbl,
                         float* __restrict__ dmul, float* __restrict__ dsum) {
    unsigned t = blockIdx.x * 256u + threadIdx.x;
    unsigned e = t >> 5, lane = t & 31u;
    if (e >= N_LBL) return;
    int a = elbl[e], b = elbl[N_LBL + e];
    float2 za = reinterpret_cast<const float2*>(z + (size_t)a * 64)[lane];
    float2 zb = reinterpret_cast<const float2*>(z + (size_t)b * 64)[lane];
    float2 m = make_float2(za.x * zb.x, za.y * zb.y);
    reinterpret_cast<float2*>(dmul + (size_t)e * 64)[lane] = m;
    float s = m.x + m.y;
#pragma unroll
    for (int o = 16; o > 0; o >>= 1) s += __shfl_xor_sync(0xffffffffu, s, o);
    if (lane == 0) dsum[e] = s;
}

// ============================================================
// split z into exact bf16 triple: z = h + m + l
// ============================================================
__global__ void k_split(const float* __restrict__ z) {
    int i = blockIdx.x * 256 + threadIdx.x;   // 1048576 elems, grid 4096
    float v = z[i];
    __nv_bfloat16 h = __float2bfloat16(v);
    float r1 = v - __bfloat162float(h);
    __nv_bfloat16 m = __float2bfloat16(r1);
    float r2 = r1 - __bfloat162float(m);
    __nv_bfloat16 l = __float2bfloat16(r2);
    g_zh[i] = h; g_zm[i] = m; g_zl[i] = l;
}

// ============================================================
// mma.sync helpers (plain PTX, valid on non-'a' sm_103 target)
// ============================================================
__device__ __forceinline__ uint32_t smem_u32(const void* p) {
    uint32_t a;
    asm("{ .reg .u64 t; cvta.to.shared.u64 t, %1; cvt.u32.u64 %0, t; }" : "=r"(a) : "l"(p));
    return a;
}
__device__ __forceinline__ void ldmx4(uint32_t* r, uint32_t addr) {
    asm volatile("ldmatrix.sync.aligned.m8n8.x4.shared.b16 {%0,%1,%2,%3}, [%4];"
                 : "=r"(r[0]), "=r"(r[1]), "=r"(r[2]), "=r"(r[3]) : "r"(addr));
}
__device__ __forceinline__ void mma_bf16(float* d, const uint32_t* a, uint32_t b0, uint32_t b1) {
    asm volatile("mma.sync.aligned.m16n8k16.row.col.f32.bf16.bf16.f32 "
                 "{%0,%1,%2,%3}, {%4,%5,%6,%7}, {%8,%9}, {%0,%1,%2,%3};"
                 : "+f"(d[0]), "+f"(d[1]), "+f"(d[2]), "+f"(d[3])
                 : "r"(a[0]), "r"(a[1]), "r"(a[2]), "r"(a[3]), "r"(b0), "r"(b1));
}

// ============================================================
// big GEMM: prob_adj = z @ z^T via exact bf16 3-split, mma.sync HMMA.
// CTA tile 128x128, 8 warps (4 M x 2 N), warp tile 32x64.
// Products grouped by B array so each fragment batch is loaded once:
//   B=h: {hh, mh, lh}   B=m: {hm, mm}   B=l: {hl}
// A fragments for all 3 arrays cached per k-step (24 regs).
// LDSM per warp-kstep: 6 (A) + 12 (B) = 18  (was 36).
// ============================================================
#define SMEM_MM 98304

__global__ void __launch_bounds__(256, 2) k_bigmm_mma(float* __restrict__ padj,
                                                      float* __restrict__ maskp) {
    extern __shared__ char smem[];
    const uint32_t sA = smem_u32(smem);
    const uint32_t sB = sA + 49152;
    const int tid = threadIdx.x;
    const int wid = tid >> 5, lane = tid & 31;
    const int bi = blockIdx.y, bj = blockIdx.x;

    // ---- fill A tiles: 3 arrays x 128 rows x 8 x 16B chunks ----
    for (int i = tid; i < 3072; i += 256) {
        int arr = i >> 10, rem = i & 1023;
        int r = rem >> 3, c = rem & 7;
        const __nv_bfloat16* src = (arr == 0) ? g_zh : (arr == 1) ? g_zm : g_zl;
        uint4 v = reinterpret_cast<const uint4*>(src + (size_t)(bi * 128 + r) * 64)[c];
        *reinterpret_cast<uint4*>(smem + arr * 16384 + r * 128 + ((c ^ (r & 7)) << 4)) = v;
    }
    // ---- fill B tiles ----
    for (int i = tid; i < 3072; i += 256) {
        int arr = i >> 10, rem = i & 1023;
        int r = rem >> 3, c = rem & 7;
        const __nv_bfloat16* src = (arr == 0) ? g_zh : (arr == 1) ? g_zm : g_zl;
        uint4 v = reinterpret_cast<const uint4*>(src + (size_t)(bj * 128 + r) * 64)[c];
        *reinterpret_cast<uint4*>(smem + 49152 + arr * 16384 + r * 128 + ((c ^ (r & 7)) << 4)) = v;
    }
    __syncthreads();

    const int wm = (wid & 3) * 32;   // warp M offset
    const int wn = (wid >> 2) * 64;  // warp N offset
    const int lm = lane & 15, lh = lane >> 4;

    float acc[2][8][4];
#pragma unroll
    for (int mi = 0; mi < 2; mi++)
#pragma unroll
        for (int jj = 0; jj < 8; jj++)
#pragma unroll
            for (int q = 0; q < 4; q++) acc[mi][jj][q] = 0.f;

    // products per B group: B=h -> A {h,m,l}; B=m -> A {h,m}; B=l -> A {h}
    const int NApg[3] = {3, 2, 1};

#pragma unroll
    for (int ks = 0; ks < 4; ks++) {
        const int ch = ks * 2 + lh;          // 16B k-chunk index (0..7)
        uint32_t af[3][2][4];
#pragma unroll
        for (int arr = 0; arr < 3; arr++)
#pragma unroll
            for (int mi = 0; mi < 2; mi++) {
                int r = wm + mi * 16 + lm;
                ldmx4(af[arr][mi], sA + arr * 16384 + r * 128 + ((ch ^ (r & 7)) << 4));
            }
#pragma unroll
        for (int g = 0; g < 3; g++) {
            uint32_t bfr[4][4];
#pragma unroll
            for (int nb = 0; nb < 4; nb++) {
                int r = wn + nb * 16 + lm;
                ldmx4(bfr[nb], sB + g * 16384 + r * 128 + ((ch ^ (r & 7)) << 4));
            }
#pragma unroll
            for (int a = 0; a < 3; a++) {
                if (a < NApg[g]) {
#pragma unroll
                    for (int mi = 0; mi < 2; mi++)
#pragma unroll
                        for (int nb = 0; nb < 4; nb++) {
                            mma_bf16(acc[mi][nb * 2 + 0], af[a][mi], bfr[nb][0], bfr[nb][2]);
                            mma_bf16(acc[mi][nb * 2 + 1], af[a][mi], bfr[nb][1], bfr[nb][3]);
                        }
                }
            }
        }
    }

    // ---- epilogue: direct float2 stores ----
    const int rowb = bi * 128 + wm + (lane >> 2);
    const int colb = bj * 128 + wn + (lane & 3) * 2;
#pragma unroll
    for (int mi = 0; mi < 2; mi++) {
#pragma unroll
        for (int jj = 0; jj < 8; jj++) {
            const float* d = acc[mi][jj];
            size_t o0 = (size_t)(rowb + mi * 16) * 16384ull + colb + jj * 8;
            size_t o1 = o0 + 8ull * 16384ull;
            float2 v0 = make_float2(d[0], d[1]);
            float2 v1 = make_float2(d[2], d[3]);
            __stcs(reinterpret_cast<float2*>(padj + o0), v0);
            __stcs(reinterpret_cast<float2*>(padj + o1), v1);
            float2 m0 = make_float2(v0.x > 0.f ? 1.f : 0.f, v0.y > 0.f ? 1.f : 0.f);
            float2 m1 = make_float2(v1.x > 0.f ? 1.f : 0.f, v1.y > 0.f ? 1.f : 0.f);
            __stcs(reinterpret_cast<float2*>(maskp + o0), m0);
            __stcs(reinterpret_cast<float2*>(maskp + o1), m1);
        }
    }
}

// ============================================================
extern "C" void kernel_launch(void* const* d_in, const int* in_sizes, int n_in,
                              void* d_out, int out_size) {
    const float* x   = (const float*)d_in[0];
    const int*   ei  = (const int*)d_in[1];
    const int*   elb = (const int*)d_in[2];
    const float* Wl1 = (const float*)d_in[3];
    const float* bl1 = (const float*)d_in[4];
    const float* Wr1 = (const float*)d_in[5];
    const float* Wl2 = (const float*)d_in[6];
    const float* bl2 = (const float*)d_in[7];
    const float* Wr2 = (const float*)d_in[8];

    float* out   = (float*)d_out;
    float* sage1 = out + O_SAGE1;
    float* z     = out + O_Z;
    float* dmul  = out + O_DMUL;
    float* dsum  = out + O_DSUM;
    float* padj  = out + O_PADJ;
    float* maskp = out + O_MASK;

    (void)cudaFuncSetAttribute(k_bigmm_mma, cudaFuncAttributeMaxDynamicSharedMemorySize, SMEM_MM);

    k_zero<<<4112, 256>>>();
    k_scatter1<<<65536, 256>>>(x, ei, ei + N_EDGES);
    k_invdeg<<<64, 256>>>();
    k_gemm1<<<256, 256>>>(x, Wl1, Wr1, bl1, sage1);
    k_scatter2<<<65536, 256>>>(sage1, ei, ei + N_EDGES);
    k_gemm2<<<512, 256>>>(sage1, Wl2, Wr2, bl2, z);
    k_split<<<4096, 256>>>(z);
    k_decode<<<16384, 256>>>(z, elb, dmul, dsum);
    k_bigmm_mma<<<dim3(128, 128), 256, SMEM_MM>>>(padj, maskp);
}

// round 11
// speedup vs baseline: 2.0474x; 1.3218x over previous
#include <cuda_runtime.h>
#include <cuda_bf16.h>
#include <cstdint>

typedef unsigned long long ull;

#define N_NODES 16384
#define N_EDGES 524288
#define N_LBL   131072

// ---- output layout (flattened float32 concat in reference-return order) ----
#define O_SAGE1 0ull
#define L_SAGE1 (16384ull*128ull)
#define O_Z     (O_SAGE1 + L_SAGE1)
#define L_Z     (16384ull*64ull)
#define O_DMUL  (O_Z + L_Z)
#define L_DMUL  (131072ull*64ull)
#define O_DSUM  (O_DMUL + L_DMUL)
#define L_DSUM  (131072ull)
#define O_PADJ  (O_DSUM + L_DSUM)
#define L_PADJ  (16384ull*16384ull)
#define O_MASK  (O_PADJ + L_PADJ)

// ---- scratch (device globals; no allocation allowed) ----
__device__ __align__(16) float g_agg1[N_NODES * 128];
__device__ __align__(16) float g_agg2[N_NODES * 128];
__device__ __align__(16) float g_deg[N_NODES];
__device__ __align__(16) float g_invdeg[N_NODES];
// exact 3-way bf16 split of z: z = h + m + l
__device__ __align__(16) __nv_bfloat16 g_zh[N_NODES * 64];
__device__ __align__(16) __nv_bfloat16 g_zm[N_NODES * 64];
__device__ __align__(16) __nv_bfloat16 g_zl[N_NODES * 64];

// ============================================================
// zero scratch
// ============================================================
__global__ void k_zero() {
    unsigned i = blockIdx.x * 256u + threadIdx.x;
    float4 zv = make_float4(0.f, 0.f, 0.f, 0.f);
    if (i < 524288u) {
        reinterpret_cast<float4*>(g_agg1)[i] = zv;
    } else if (i < 1048576u) {
        reinterpret_cast<float4*>(g_agg2)[i - 524288u] = zv;
    } else if (i < 1052672u) {
        reinterpret_cast<float4*>(g_deg)[i - 1048576u] = zv;
    }
}

// ============================================================
// scatter-add: one warp per edge, float4 vector atomics (sm_90+)
// ============================================================
__device__ __forceinline__ void scatter_body(const float* __restrict__ feat,
                                             const int* __restrict__ src,
                                             const int* __restrict__ dst,
                                             float* agg, float* deg, int addDeg) {
    unsigned t = blockIdx.x * 256u + threadIdx.x;
    unsigned e = t >> 5, lane = t & 31u;
    if (e >= N_EDGES) return;
    int s = src[e], d = dst[e];
    float4 v = reinterpret_cast<const float4*>(feat + (size_t)s * 128)[lane];
    atomicAdd(reinterpret_cast<float4*>(agg + (size_t)d * 128 + lane * 4), v);
    if (addDeg && lane == 0) atomicAdd(deg + d, 1.0f);
}

__global__ void k_scatter1(const float* __restrict__ x,
                           const int* __restrict__ src, const int* __restrict__ dst) {
    scatter_body(x, src, dst, g_agg1, g_deg, 1);
}
__global__ void k_scatter2(const float* __restrict__ sage1,
                           const int* __restrict__ src, const int* __restrict__ dst) {
    scatter_body(sage1, src, dst, g_agg2, g_deg, 0);
}

__global__ void k_invdeg() {
    int i = blockIdx.x * 256 + threadIdx.x;
    if (i < N_NODES) g_invdeg[i] = 1.0f / fmaxf(g_deg[i], 1.0f);
}

// ============================================================
// Layer 1: sage1 = relu( mean1 @ W_l1 + b_l1 + x @ W_r1 )
// Block 64 rows x 128 cols, 256 threads, thread tile 4x8.
// ============================================================
#define YS_STRIDE 68
__global__ void __launch_bounds__(256) k_gemm1(const float* __restrict__ x,
                                               const float* __restrict__ Wl,
                                               const float* __restrict__ Wr,
                                               const float* __restrict__ bias,
                                               float* __restrict__ out) {
    __shared__ float Ws[64 * 128];
    __shared__ float Ys[64 * YS_STRIDE];
    const int t = threadIdx.x;
    const int row0 = blockIdx.x * 64;
    const int tr = t >> 4, tc = t & 15;

    float acc[4][8];
#pragma unroll
    for (int jj = 0; jj < 8; jj++) {
        float bv = bias[tc * 8 + jj];
#pragma unroll
        for (int ii = 0; ii < 4; ii++) acc[ii][jj] = bv;
    }

    for (int c = 0; c < 4; c++) {
        for (int i = t; i < 2048; i += 256) {
            int l = i >> 5, q = i & 31;
            int g = c * 64 + l;
            float4 v = (g < 128)
                ? reinterpret_cast<const float4*>(Wl + (size_t)g * 128)[q]
                : reinterpret_cast<const float4*>(Wr + (size_t)(g - 128) * 128)[q];
            reinterpret_cast<float4*>(Ws + l * 128)[q] = v;
        }
        for (int i = t; i < 1024; i += 256) {
            int r = i >> 4, q = i & 15;
            int n = row0 + r;
            float4 v;
            if (c < 2) {
                v = reinterpret_cast<const float4*>(g_agg1 + (size_t)n * 128 + c * 64)[q];
                float s = g_invdeg[n];
                v.x *= s; v.y *= s; v.z *= s; v.w *= s;
            } else {
                v = reinterpret_cast<const float4*>(x + (size_t)n * 128 + (c - 2) * 64)[q];
            }
            reinterpret_cast<float4*>(Ys + r * YS_STRIDE)[q] = v;
        }
        __syncthreads();
#pragma unroll 4
        for (int k = 0; k < 64; k++) {
            float a[4];
#pragma unroll
            for (int ii = 0; ii < 4; ii++) a[ii] = Ys[(4 * tr + ii) * YS_STRIDE + k];
            float w[8];
            *reinterpret_cast<float4*>(w)     = *reinterpret_cast<const float4*>(Ws + k * 128 + tc * 8);
            *reinterpret_cast<float4*>(w + 4) = *reinterpret_cast<const float4*>(Ws + k * 128 + tc * 8 + 4);
#pragma unroll
            for (int ii = 0; ii < 4; ii++)
#pragma unroll
                for (int jj = 0; jj < 8; jj++) acc[ii][jj] = fmaf(a[ii], w[jj], acc[ii][jj]);
        }
        __syncthreads();
    }
#pragma unroll
    for (int ii = 0; ii < 4; ii++) {
        size_t off = (size_t)(row0 + 4 * tr + ii) * 128 + tc * 8;
        float4 v0 = make_float4(fmaxf(acc[ii][0], 0.f), fmaxf(acc[ii][1], 0.f),
                                fmaxf(acc[ii][2], 0.f), fmaxf(acc[ii][3], 0.f));
        float4 v1 = make_float4(fmaxf(acc[ii][4], 0.f), fmaxf(acc[ii][5], 0.f),
                                fmaxf(acc[ii][6], 0.f), fmaxf(acc[ii][7], 0.f));
        *reinterpret_cast<float4*>(out + off)     = v0;
        *reinterpret_cast<float4*>(out + off + 4) = v1;
    }
}

// ============================================================
// Layer 2: z = mean2 @ W_l2 + b_l2 + sage1 @ W_r2
// ============================================================
__global__ void __launch_bounds__(256) k_gemm2(const float* __restrict__ sage1,
                                               const float* __restrict__ Wl,
                                               const float* __restrict__ Wr,
                                               const float* __restrict__ bias,
                                               float* __restrict__ out) {
    __shared__ float Ws[64 * 64];
    __shared__ float Ys[32 * YS_STRIDE];
    const int t = threadIdx.x;
    const int row0 = blockIdx.x * 32;
    const int tr = t >> 3, tc = t & 7;

    float acc[8];
#pragma unroll
    for (int jj = 0; jj < 8; jj++) acc[jj] = bias[tc * 8 + jj];

    for (int c = 0; c < 4; c++) {
        for (int i = t; i < 1024; i += 256) {
            int l = i >> 4, q = i & 15;
            int g = c * 64 + l;
            float4 v = (g < 128)
                ? reinterpret_cast<const float4*>(Wl + (size_t)g * 64)[q]
                : reinterpret_cast<const float4*>(Wr + (size_t)(g - 128) * 64)[q];
            reinterpret_cast<float4*>(Ws + l * 64)[q] = v;
        }
        for (int i = t; i < 512; i += 256) {
            int r = i >> 4, q = i & 15;
            int n = row0 + r;
            float4 v;
            if (c < 2) {
                v = reinterpret_cast<const float4*>(g_agg2 + (size_t)n * 128 + c * 64)[q];
                float s = g_invdeg[n];
                v.x *= s; v.y *= s; v.z *= s; v.w *= s;
            } else {
                v = reinterpret_cast<const float4*>(sage1 + (size_t)n * 128 + (c - 2) * 64)[q];
            }
            reinterpret_cast<float4*>(Ys + r * YS_STRIDE)[q] = v;
        }
        __syncthreads();
#pragma unroll 8
        for (int k = 0; k < 64; k++) {
            float a = Ys[tr * YS_STRIDE + k];
            float w[8];
            *reinterpret_cast<float4*>(w)     = *reinterpret_cast<const float4*>(Ws + k * 64 + tc * 8);
            *reinterpret_cast<float4*>(w + 4) = *reinterpret_cast<const float4*>(Ws + k * 64 + tc * 8 + 4);
#pragma unroll
            for (int jj = 0; jj < 8; jj++) acc[jj] = fmaf(a, w[jj], acc[jj]);
        }
        __syncthreads();
    }
    size_t off = (size_t)(row0 + tr) * 64 + tc * 8;
    float4 v0 = make_float4(acc[0], acc[1], acc[2], acc[3]);
    float4 v1 = make_float4(acc[4], acc[5], acc[6], acc[7]);
    *reinterpret_cast<float4*>(out + off)     = v0;
    *reinterpret_cast<float4*>(out + off + 4) = v1;
}

// ============================================================
// decode: one warp per label edge
// ============================================================
__global__ void k_decode(const float* __restrict__ z, const int* __restrict__ elbl,
                         float* __restrict__ dmul, float* __restrict__ dsum) {
    unsigned t = blockIdx.x * 256u + threadIdx.x;
    unsigned e = t >> 5, lane = t & 31u;
    if (e >= N_LBL) return;
    int a = elbl[e], b = elbl[N_LBL + e];
    float2 za = reinterpret_cast<const float2*>(z + (size_t)a * 64)[lane];
    float2 zb = reinterpret_cast<const float2*>(z + (size_t)b * 64)[lane];
    float2 m = make_float2(za.x * zb.x, za.y * zb.y);
    reinterpret_cast<float2*>(dmul + (size_t)e * 64)[lane] = m;
    float s = m.x + m.y;
#pragma unroll
    for (int o = 16; o > 0; o >>= 1) s += __shfl_xor_sync(0xffffffffu, s, o);
    if (lane == 0) dsum[e] = s;
}

// ============================================================
// split z into exact bf16 triple: z = h + m + l
// ============================================================
__global__ void k_split(const float* __restrict__ z) {
    int i = blockIdx.x * 256 + threadIdx.x;   // 1048576 elems, grid 4096
    float v = z[i];
    __nv_bfloat16 h = __float2bfloat16(v);
    float r1 = v - __bfloat162float(h);
    __nv_bfloat16 m = __float2bfloat16(r1);
    float r2 = r1 - __bfloat162float(m);
    __nv_bfloat16 l = __float2bfloat16(r2);
    g_zh[i] = h; g_zm[i] = m; g_zl[i] = l;
}

// ============================================================
// mma.sync helpers (plain PTX, valid on non-'a' sm_103 target)
// ============================================================
__device__ __forceinline__ uint32_t smem_u32(const void* p) {
    uint32_t a;
    asm("{ .reg .u64 t; cvta.to.shared.u64 t, %1; cvt.u32.u64 %0, t; }" : "=r"(a) : "l"(p));
    return a;
}
__device__ __forceinline__ void ldmx4(uint32_t* r, uint32_t addr) {
    asm volatile("ldmatrix.sync.aligned.m8n8.x4.shared.b16 {%0,%1,%2,%3}, [%4];"
                 : "=r"(r[0]), "=r"(r[1]), "=r"(r[2]), "=r"(r[3]) : "r"(addr));
}
__device__ __forceinline__ void mma_bf16(float* d, const uint32_t* a, uint32_t b0, uint32_t b1) {
    asm volatile("mma.sync.aligned.m16n8k16.row.col.f32.bf16.bf16.f32 "
                 "{%0,%1,%2,%3}, {%4,%5,%6,%7}, {%8,%9}, {%0,%1,%2,%3};"
                 : "+f"(d[0]), "+f"(d[1]), "+f"(d[2]), "+f"(d[3])
                 : "r"(a[0]), "r"(a[1]), "r"(a[2]), "r"(a[3]), "r"(b0), "r"(b1));
}

// ============================================================
// big GEMM (SYMMETRIC): prob_adj = z @ z^T via exact bf16 3-split.
// Only lower-triangular CTA tiles computed (8256 of 16384); off-diagonal
// CTAs also write the mirrored (bj,bi) tile via a stride-132 smem transpose
// (conflict-free STS; coalesced scalar write-out). Output bitwise identical
// to the full-grid version.
// ============================================================
#define SMEM_MM 98304
#define TSTRIDE 132

__global__ void __launch_bounds__(256, 2) k_bigmm_mma(float* __restrict__ padj,
                                                      float* __restrict__ maskp) {
    extern __shared__ char smem[];
    const uint32_t sA = smem_u32(smem);
    const uint32_t sB = sA + 49152;
    const int tid = threadIdx.x;
    const int wid = tid >> 5, lane = tid & 31;

    // triangular decode: blockIdx.x -> (bi, bj), bj <= bi
    int t = blockIdx.x;
    int bi = (int)((sqrtf(8.f * (float)t + 1.f) - 1.f) * 0.5f);
    while ((bi + 1) * (bi + 2) / 2 <= t) bi++;
    while (bi * (bi + 1) / 2 > t) bi--;
    int bj = t - bi * (bi + 1) / 2;

    // ---- fill A tiles: 3 arrays x 128 rows x 8 x 16B chunks ----
    for (int i = tid; i < 3072; i += 256) {
        int arr = i >> 10, rem = i & 1023;
        int r = rem >> 3, c = rem & 7;
        const __nv_bfloat16* src = (arr == 0) ? g_zh : (arr == 1) ? g_zm : g_zl;
        uint4 v = reinterpret_cast<const uint4*>(src + (size_t)(bi * 128 + r) * 64)[c];
        *reinterpret_cast<uint4*>(smem + arr * 16384 + r * 128 + ((c ^ (r & 7)) << 4)) = v;
    }
    // ---- fill B tiles ----
    for (int i = tid; i < 3072; i += 256) {
        int arr = i >> 10, rem = i & 1023;
        int r = rem >> 3, c = rem & 7;
        const __nv_bfloat16* src = (arr == 0) ? g_zh : (arr == 1) ? g_zm : g_zl;
        uint4 v = reinterpret_cast<const uint4*>(src + (size_t)(bj * 128 + r) * 64)[c];
        *reinterpret_cast<uint4*>(smem + 49152 + arr * 16384 + r * 128 + ((c ^ (r & 7)) << 4)) = v;
    }
    __syncthreads();

    const int wm = (wid & 3) * 32;   // warp M offset
    const int wn = (wid >> 2) * 64;  // warp N offset
    const int lm = lane & 15, lh = lane >> 4;

    float acc[2][8][4];
#pragma unroll
    for (int mi = 0; mi < 2; mi++)
#pragma unroll
        for (int jj = 0; jj < 8; jj++)
#pragma unroll
            for (int q = 0; q < 4; q++) acc[mi][jj][q] = 0.f;

    // products per B group: B=h -> A {h,m,l}; B=m -> A {h,m}; B=l -> A {h}
    const int NApg[3] = {3, 2, 1};

#pragma unroll
    for (int ks = 0; ks < 4; ks++) {
        const int ch = ks * 2 + lh;          // 16B k-chunk index (0..7)
        uint32_t af[3][2][4];
#pragma unroll
        for (int arr = 0; arr < 3; arr++)
#pragma unroll
            for (int mi = 0; mi < 2; mi++) {
                int r = wm + mi * 16 + lm;
                ldmx4(af[arr][mi], sA + arr * 16384 + r * 128 + ((ch ^ (r & 7)) << 4));
            }
#pragma unroll
        for (int g = 0; g < 3; g++) {
            uint32_t bfr[4][4];
#pragma unroll
            for (int nb = 0; nb < 4; nb++) {
                int r = wn + nb * 16 + lm;
                ldmx4(bfr[nb], sB + g * 16384 + r * 128 + ((ch ^ (r & 7)) << 4));
            }
#pragma unroll
            for (int a = 0; a < 3; a++) {
                if (a < NApg[g]) {
#pragma unroll
                    for (int mi = 0; mi < 2; mi++)
#pragma unroll
                        for (int nb = 0; nb < 4; nb++) {
                            mma_bf16(acc[mi][nb * 2 + 0], af[a][mi], bfr[nb][0], bfr[nb][2]);
                            mma_bf16(acc[mi][nb * 2 + 1], af[a][mi], bfr[nb][1], bfr[nb][3]);
                        }
                }
            }
        }
    }

    // ---- direct write of block (bi, bj) ----
    const int rl = wm + (lane >> 2);          // local row 0..127 (of first mi)
    const int cl = wn + (lane & 3) * 2;       // local col 0..127
    const int rowb = bi * 128 + rl;
    const int colb = bj * 128 + cl;
#pragma unroll
    for (int mi = 0; mi < 2; mi++) {
#pragma unroll
        for (int jj = 0; jj < 8; jj++) {
            const float* d = acc[mi][jj];
            size_t o0 = (size_t)(rowb + mi * 16) * 16384ull + colb + jj * 8;
            size_t o1 = o0 + 8ull * 16384ull;
            float2 v0 = make_float2(d[0], d[1]);
            float2 v1 = make_float2(d[2], d[3]);
            __stcs(reinterpret_cast<float2*>(padj + o0), v0);
            __stcs(reinterpret_cast<float2*>(padj + o1), v1);
            float2 m0 = make_float2(v0.x > 0.f ? 1.f : 0.f, v0.y > 0.f ? 1.f : 0.f);
            float2 m1 = make_float2(v1.x > 0.f ? 1.f : 0.f, v1.y > 0.f ? 1.f : 0.f);
            __stcs(reinterpret_cast<float2*>(maskp + o0), m0);
            __stcs(reinterpret_cast<float2*>(maskp + o1), m1);
        }
    }

    // ---- mirrored write of block (bj, bi) via smem transpose ----
    if (bi != bj) {
        __syncthreads();   // mainloop smem reads done; safe to reuse as transpose buffer
        float* smt = reinterpret_cast<float*>(smem);
        // store acc transposed: smt[c * TSTRIDE + r]
#pragma unroll
        for (int mi = 0; mi < 2; mi++) {
#pragma unroll
            for (int jj = 0; jj < 8; jj++) {
                const float* d = acc[mi][jj];
                int r = rl + mi * 16;
                int c = cl + jj * 8;
                smt[(c + 0) * TSTRIDE + r]     = d[0];
                smt[(c + 1) * TSTRIDE + r]     = d[1];
                smt[(c + 0) * TSTRIDE + r + 8] = d[2];
                smt[(c + 1) * TSTRIDE + r + 8] = d[3];
            }
        }
        __syncthreads();
        // coalesced write-out: row r of mirror = local col r of original
        for (int i = tid; i < 16384; i += 256) {
            int r = i >> 7, c = i & 127;
            float v = smt[r * TSTRIDE + c];
            size_t o = (size_t)(bj * 128 + r) * 16384ull + (size_t)bi * 128 + c;
            __stcs(padj + o, v);
            __stcs(maskp + o, v > 0.f ? 1.f : 0.f);
        }
    }
}

// ============================================================
extern "C" void kernel_launch(void* const* d_in, const int* in_sizes, int n_in,
                              void* d_out, int out_size) {
    const float* x   = (const float*)d_in[0];
    const int*   ei  = (const int*)d_in[1];
    const int*   elb = (const int*)d_in[2];
    const float* Wl1 = (const float*)d_in[3];
    const float* bl1 = (const float*)d_in[4];
    const float* Wr1 = (const float*)d_in[5];
    const float* Wl2 = (const float*)d_in[6];
    const float* bl2 = (const float*)d_in[7];
    const float* Wr2 = (const float*)d_in[8];

    float* out   = (float*)d_out;
    float* sage1 = out + O_SAGE1;
    float* z     = out + O_Z;
    float* dmul  = out + O_DMUL;
    float* dsum  = out + O_DSUM;
    float* padj  = out + O_PADJ;
    float* maskp = out + O_MASK;

    (void)cudaFuncSetAttribute(k_bigmm_mma, cudaFuncAttributeMaxDynamicSharedMemorySize, SMEM_MM);

    k_zero<<<4112, 256>>>();
    k_scatter1<<<65536, 256>>>(x, ei, ei + N_EDGES);
    k_invdeg<<<64, 256>>>();
    k_gemm1<<<256, 256>>>(x, Wl1, Wr1, bl1, sage1);
    k_scatter2<<<65536, 256>>>(sage1, ei, ei + N_EDGES);
    k_gemm2<<<512, 256>>>(sage1, Wl2, Wr2, bl2, z);
    k_split<<<4096, 256>>>(z);
    k_decode<<<16384, 256>>>(z, elb, dmul, dsum);
    k_bigmm_mma<<<8256, 256, SMEM_MM>>>(padj, maskp);
}

// round 12
// speedup vs baseline: 2.4224x; 1.1832x over previous
#include <cuda_runtime.h>
#include <cuda_fp16.h>
#include <cstdint>

typedef unsigned long long ull;

#define N_NODES 16384
#define N_EDGES 524288
#define N_LBL   131072

// ---- output layout (flattened float32 concat in reference-return order) ----
#define O_SAGE1 0ull
#define L_SAGE1 (16384ull*128ull)
#define O_Z     (O_SAGE1 + L_SAGE1)
#define L_Z     (16384ull*64ull)
#define O_DMUL  (O_Z + L_Z)
#define L_DMUL  (131072ull*64ull)
#define O_DSUM  (O_DMUL + L_DMUL)
#define L_DSUM  (131072ull)
#define O_PADJ  (O_DSUM + L_DSUM)
#define L_PADJ  (16384ull*16384ull)
#define O_MASK  (O_PADJ + L_PADJ)

// ---- scratch (device globals; no allocation allowed) ----
__device__ __align__(16) float g_agg1[N_NODES * 128];   // also reused as y1 [N,64]
__device__ __align__(16) float g_agg2[N_NODES * 64];
__device__ __align__(16) float g_deg[N_NODES];
__device__ __align__(16) float g_invdeg[N_NODES];
// exact 2-way fp16 split of z: z = h + m (residual ~2^-23 |z|)
__device__ __align__(16) __half g_zh[N_NODES * 64];
__device__ __align__(16) __half g_zm[N_NODES * 64];

// ============================================================
// zero scratch: g_agg1 (524288 f4) + g_agg2 (262144 f4) + deg (4096 f4)
// ============================================================
__global__ void k_zero() {
    unsigned i = blockIdx.x * 256u + threadIdx.x;
    float4 zv = make_float4(0.f, 0.f, 0.f, 0.f);
    if (i < 524288u) {
        reinterpret_cast<float4*>(g_agg1)[i] = zv;
    } else if (i < 786432u) {
        reinterpret_cast<float4*>(g_agg2)[i - 524288u] = zv;
    } else if (i < 790528u) {
        reinterpret_cast<float4*>(g_deg)[i - 786432u] = zv;
    }
}

// ============================================================
// scatter1: one warp per edge, 128 ch, float4 vector atomics
// ============================================================
__global__ void k_scatter1(const float* __restrict__ x,
                           const int* __restrict__ src, const int* __restrict__ dst) {
    unsigned t = blockIdx.x * 256u + threadIdx.x;
    unsigned e = t >> 5, lane = t & 31u;
    if (e >= N_EDGES) return;
    int s = src[e], d = dst[e];
    float4 v = reinterpret_cast<const float4*>(x + (size_t)s * 128)[lane];
    atomicAdd(reinterpret_cast<float4*>(g_agg1 + (size_t)d * 128 + lane * 4), v);
    if (lane == 0) atomicAdd(g_deg + d, 1.0f);
}

// ============================================================
// scatter2: half-warp per edge, 64 ch (y1 = sage1 @ W_l2 pre-applied)
// ============================================================
__global__ void k_scatter2(const int* __restrict__ src, const int* __restrict__ dst) {
    unsigned t = blockIdx.x * 256u + threadIdx.x;
    unsigned e = t >> 4, lane = t & 15u;
    if (e >= N_EDGES) return;
    int s = src[e], d = dst[e];
    float4 v = reinterpret_cast<const float4*>(g_agg1 + (size_t)s * 64)[lane];
    atomicAdd(reinterpret_cast<float4*>(g_agg2 + (size_t)d * 64 + lane * 4), v);
}

__global__ void k_invdeg() {
    int i = blockIdx.x * 256 + threadIdx.x;
    if (i < N_NODES) g_invdeg[i] = 1.0f / fmaxf(g_deg[i], 1.0f);
}

// ============================================================
// Layer 1: sage1 = relu( mean1 @ W_l1 + b_l1 + x @ W_r1 )
// Block 64 rows x 128 cols, 256 threads, thread tile 4x8.
// ============================================================
#define YS_STRIDE 68
__global__ void __launch_bounds__(256) k_gemm1(const float* __restrict__ x,
                                               const float* __restrict__ Wl,
                                               const float* __restrict__ Wr,
                                               const float* __restrict__ bias,
                                               float* __restrict__ out) {
    __shared__ float Ws[64 * 128];
    __shared__ float Ys[64 * YS_STRIDE];
    const int t = threadIdx.x;
    const int row0 = blockIdx.x * 64;
    const int tr = t >> 4, tc = t & 15;

    float acc[4][8];
#pragma unroll
    for (int jj = 0; jj < 8; jj++) {
        float bv = bias[tc * 8 + jj];
#pragma unroll
        for (int ii = 0; ii < 4; ii++) acc[ii][jj] = bv;
    }

    for (int c = 0; c < 4; c++) {
        for (int i = t; i < 2048; i += 256) {
            int l = i >> 5, q = i & 31;
            int g = c * 64 + l;
            float4 v = (g < 128)
                ? reinterpret_cast<const float4*>(Wl + (size_t)g * 128)[q]
                : reinterpret_cast<const float4*>(Wr + (size_t)(g - 128) * 128)[q];
            reinterpret_cast<float4*>(Ws + l * 128)[q] = v;
        }
        for (int i = t; i < 1024; i += 256) {
            int r = i >> 4, q = i & 15;
            int n = row0 + r;
            float4 v;
            if (c < 2) {
                v = reinterpret_cast<const float4*>(g_agg1 + (size_t)n * 128 + c * 64)[q];
                float s = g_invdeg[n];
                v.x *= s; v.y *= s; v.z *= s; v.w *= s;
            } else {
                v = reinterpret_cast<const float4*>(x + (size_t)n * 128 + (c - 2) * 64)[q];
            }
            reinterpret_cast<float4*>(Ys + r * YS_STRIDE)[q] = v;
        }
        __syncthreads();
#pragma unroll 4
        for (int k = 0; k < 64; k++) {
            float a[4];
#pragma unroll
            for (int ii = 0; ii < 4; ii++) a[ii] = Ys[(4 * tr + ii) * YS_STRIDE + k];
            float w[8];
            *reinterpret_cast<float4*>(w)     = *reinterpret_cast<const float4*>(Ws + k * 128 + tc * 8);
            *reinterpret_cast<float4*>(w + 4) = *reinterpret_cast<const float4*>(Ws + k * 128 + tc * 8 + 4);
#pragma unroll
            for (int ii = 0; ii < 4; ii++)
#pragma unroll
                for (int jj = 0; jj < 8; jj++) acc[ii][jj] = fmaf(a[ii], w[jj], acc[ii][jj]);
        }
        __syncthreads();
    }
#pragma unroll
    for (int ii = 0; ii < 4; ii++) {
        size_t off = (size_t)(row0 + 4 * tr + ii) * 128 + tc * 8;
        float4 v0 = make_float4(fmaxf(acc[ii][0], 0.f), fmaxf(acc[ii][1], 0.f),
                                fmaxf(acc[ii][2], 0.f), fmaxf(acc[ii][3], 0.f));
        float4 v1 = make_float4(fmaxf(acc[ii][4], 0.f), fmaxf(acc[ii][5], 0.f),
                                fmaxf(acc[ii][6], 0.f), fmaxf(acc[ii][7], 0.f));
        *reinterpret_cast<float4*>(out + off)     = v0;
        *reinterpret_cast<float4*>(out + off + 4) = v1;
    }
}

// ============================================================
// gemm_pre: y1 = sage1 @ W_l2  ([N,128]@[128,64] -> g_agg1 as [N,64])
// Block 32 rows x 64 cols, thread tile 1x8.
// ============================================================
__global__ void __launch_bounds__(256) k_gemm_pre(const float* __restrict__ sage1,
                                                  const float* __restrict__ Wl) {
    __shared__ float Ws[64 * 64];
    __shared__ float Ys[32 * YS_STRIDE];
    const int t = threadIdx.x;
    const int row0 = blockIdx.x * 32;
    const int tr = t >> 3, tc = t & 7;

    float acc[8];
#pragma unroll
    for (int jj = 0; jj < 8; jj++) acc[jj] = 0.f;

    for (int c = 0; c < 2; c++) {
        for (int i = t; i < 1024; i += 256) {
            int l = i >> 4, q = i & 15;
            reinterpret_cast<float4*>(Ws + l * 64)[q] =
                reinterpret_cast<const float4*>(Wl + (size_t)(c * 64 + l) * 64)[q];
        }
        for (int i = t; i < 512; i += 256) {
            int r = i >> 4, q = i & 15;
            reinterpret_cast<float4*>(Ys + r * YS_STRIDE)[q] =
                reinterpret_cast<const float4*>(sage1 + (size_t)(row0 + r) * 128 + c * 64)[q];
        }
        __syncthreads();
#pragma unroll 8
        for (int k = 0; k < 64; k++) {
            float a = Ys[tr * YS_STRIDE + k];
            float w[8];
            *reinterpret_cast<float4*>(w)     = *reinterpret_cast<const float4*>(Ws + k * 64 + tc * 8);
            *reinterpret_cast<float4*>(w + 4) = *reinterpret_cast<const float4*>(Ws + k * 64 + tc * 8 + 4);
#pragma unroll
            for (int jj = 0; jj < 8; jj++) acc[jj] = fmaf(a, w[jj], acc[jj]);
        }
        __syncthreads();
    }
    size_t off = (size_t)(row0 + tr) * 64 + tc * 8;
    *reinterpret_cast<float4*>(g_agg1 + off)     = make_float4(acc[0], acc[1], acc[2], acc[3]);
    *reinterpret_cast<float4*>(g_agg1 + off + 4) = make_float4(acc[4], acc[5], acc[6], acc[7]);
}

// ============================================================
// Layer 2: z = mean(y1-agg) + b_l2 + sage1 @ W_r2  (K=128)
// ============================================================
__global__ void __launch_bounds__(256) k_gemm2(const float* __restrict__ sage1,
                                               const float* __restrict__ Wr,
                                               const float* __restrict__ bias,
                                               float* __restrict__ out) {
    __shared__ float Ws[64 * 64];
    __shared__ float Ys[32 * YS_STRIDE];
    const int t = threadIdx.x;
    const int row0 = blockIdx.x * 32;
    const int tr = t >> 3, tc = t & 7;

    const int n = row0 + tr;
    const float sdeg = g_invdeg[n];
    float acc[8];
    {
        float4 a0 = reinterpret_cast<const float4*>(g_agg2 + (size_t)n * 64 + tc * 8)[0];
        float4 a1 = reinterpret_cast<const float4*>(g_agg2 + (size_t)n * 64 + tc * 8)[1];
        acc[0] = bias[tc * 8 + 0] + sdeg * a0.x;
        acc[1] = bias[tc * 8 + 1] + sdeg * a0.y;
        acc[2] = bias[tc * 8 + 2] + sdeg * a0.z;
        acc[3] = bias[tc * 8 + 3] + sdeg * a0.w;
        acc[4] = bias[tc * 8 + 4] + sdeg * a1.x;
        acc[5] = bias[tc * 8 + 5] + sdeg * a1.y;
        acc[6] = bias[tc * 8 + 6] + sdeg * a1.z;
        acc[7] = bias[tc * 8 + 7] + sdeg * a1.w;
    }

    for (int c = 0; c < 2; c++) {
        for (int i = t; i < 1024; i += 256) {
            int l = i >> 4, q = i & 15;
            reinterpret_cast<float4*>(Ws + l * 64)[q] =
                reinterpret_cast<const float4*>(Wr + (size_t)(c * 64 + l) * 64)[q];
        }
        for (int i = t; i < 512; i += 256) {
            int r = i >> 4, q = i & 15;
            reinterpret_cast<float4*>(Ys + r * YS_STRIDE)[q] =
                reinterpret_cast<const float4*>(sage1 + (size_t)(row0 + r) * 128 + c * 64)[q];
        }
        __syncthreads();
#pragma unroll 8
        for (int k = 0; k < 64; k++) {
            float a = Ys[tr * YS_STRIDE + k];
            float w[8];
            *reinterpret_cast<float4*>(w)     = *reinterpret_cast<const float4*>(Ws + k * 64 + tc * 8);
            *reinterpret_cast<float4*>(w + 4) = *reinterpret_cast<const float4*>(Ws + k * 64 + tc * 8 + 4);
#pragma unroll
            for (int jj = 0; jj < 8; jj++) acc[jj] = fmaf(a, w[jj], acc[jj]);
        }
        __syncthreads();
    }
    size_t off = (size_t)n * 64 + tc * 8;
    *reinterpret_cast<float4*>(out + off)     = make_float4(acc[0], acc[1], acc[2], acc[3]);
    *reinterpret_cast<float4*>(out + off + 4) = make_float4(acc[4], acc[5], acc[6], acc[7]);
}

// ============================================================
// decode: one warp per label edge
// ============================================================
__global__ void k_decode(const float* __restrict__ z, const int* __restrict__ elbl,
                         float* __restrict__ dmul, float* __restrict__ dsum) {
    unsigned t = blockIdx.x * 256u + threadIdx.x;
    unsigned e = t >> 5, lane = t & 31u;
    if (e >= N_LBL) return;
    int a = elbl[e], b = elbl[N_LBL + e];
    float2 za = reinterpret_cast<const float2*>(z + (size_t)a * 64)[lane];
    float2 zb = reinterpret_cast<const float2*>(z + (size_t)b * 64)[lane];
    float2 m = make_float2(za.x * zb.x, za.y * zb.y);
    reinterpret_cast<float2*>(dmul + (size_t)e * 64)[lane] = m;
    float s = m.x + m.y;
#pragma unroll
    for (int o = 16; o > 0; o >>= 1) s += __shfl_xor_sync(0xffffffffu, s, o);
    if (lane == 0) dsum[e] = s;
}

// ============================================================
// split z into exact fp16 pair: z = h + m  (residual ~2^-23 |z|)
// ============================================================
__global__ void k_split(const float* __restrict__ z) {
    int i = blockIdx.x * 256 + threadIdx.x;   // 1048576 elems, grid 4096
    float v = z[i];
    __half h = __float2half_rn(v);
    float r1 = v - __half2float(h);
    __half m = __float2half_rn(r1);
    g_zh[i] = h; g_zm[i] = m;
}

// ============================================================
// mma.sync helpers (plain PTX, valid on non-'a' sm_103 target)
// ============================================================
__device__ __forceinline__ uint32_t smem_u32(const void* p) {
    uint32_t a;
    asm("{ .reg .u64 t; cvta.to.shared.u64 t, %1; cvt.u32.u64 %0, t; }" : "=r"(a) : "l"(p));
    return a;
}
__device__ __forceinline__ void ldmx4(uint32_t* r, uint32_t addr) {
    asm volatile("ldmatrix.sync.aligned.m8n8.x4.shared.b16 {%0,%1,%2,%3}, [%4];"
                 : "=r"(r[0]), "=r"(r[1]), "=r"(r[2]), "=r"(r[3]) : "r"(addr));
}
__device__ __forceinline__ void mma_f16(float* d, const uint32_t* a, uint32_t b0, uint32_t b1) {
    asm volatile("mma.sync.aligned.m16n8k16.row.col.f32.f16.f16.f32 "
                 "{%0,%1,%2,%3}, {%4,%5,%6,%7}, {%8,%9}, {%0,%1,%2,%3};"
                 : "+f"(d[0]), "+f"(d[1]), "+f"(d[2]), "+f"(d[3])
                 : "r"(a[0]), "r"(a[1]), "r"(a[2]), "r"(a[3]), "r"(b0), "r"(b1));
}

// ============================================================
// big GEMM (SYMMETRIC + fp16 2-split): prob_adj = z @ z^T.
// Products: hh, mh (B=h group) and hm (B=m group) — dropped terms ~2^-23 rel.
// Lower-triangular CTA tiles only; mirror written via smem transpose.
// smem: A 2x16KB + B 2x16KB = 64KB; transpose buffer 128x132x4 = 66KB.
// ============================================================
#define SMEM_MM 69632
#define TSTRIDE 132

__global__ void __launch_bounds__(256, 2) k_bigmm_mma(float* __restrict__ padj,
                                                      float* __restrict__ maskp) {
    extern __shared__ char smem[];
    const uint32_t sA = smem_u32(smem);
    const uint32_t sB = sA + 32768;
    const int tid = threadIdx.x;
    const int wid = tid >> 5, lane = tid & 31;

    // triangular decode: blockIdx.x -> (bi, bj), bj <= bi
    int t = blockIdx.x;
    int bi = (int)((sqrtf(8.f * (float)t + 1.f) - 1.f) * 0.5f);
    while ((bi + 1) * (bi + 2) / 2 <= t) bi++;
    while (bi * (bi + 1) / 2 > t) bi--;
    int bj = t - bi * (bi + 1) / 2;

    // ---- fill A tiles: 2 arrays x 128 rows x 8 x 16B chunks ----
    for (int i = tid; i < 2048; i += 256) {
        int arr = i >> 10, rem = i & 1023;
        int r = rem >> 3, c = rem & 7;
        const __half* src = (arr == 0) ? g_zh : g_zm;
        uint4 v = reinterpret_cast<const uint4*>(src + (size_t)(bi * 128 + r) * 64)[c];
        *reinterpret_cast<uint4*>(smem + arr * 16384 + r * 128 + ((c ^ (r & 7)) << 4)) = v;
    }
    // ---- fill B tiles ----
    for (int i = tid; i < 2048; i += 256) {
        int arr = i >> 10, rem = i & 1023;
        int r = rem >> 3, c = rem & 7;
        const __half* src = (arr == 0) ? g_zh : g_zm;
        uint4 v = reinterpret_cast<const uint4*>(src + (size_t)(bj * 128 + r) * 64)[c];
        *reinterpret_cast<uint4*>(smem + 32768 + arr * 16384 + r * 128 + ((c ^ (r & 7)) << 4)) = v;
    }
    __syncthreads();

    const int wm = (wid & 3) * 32;   // warp M offset
    const int wn = (wid >> 2) * 64;  // warp N offset
    const int lm = lane & 15, lh = lane >> 4;

    float acc[2][8][4];
#pragma unroll
    for (int mi = 0; mi < 2; mi++)
#pragma unroll
        for (int jj = 0; jj < 8; jj++)
#pragma unroll
            for (int q = 0; q < 4; q++) acc[mi][jj][q] = 0.f;

    // B=h group (g=0): A in {h, m}; B=m group (g=1): A in {h}
    const int NApg[2] = {2, 1};

#pragma unroll
    for (int ks = 0; ks < 4; ks++) {
        const int ch = ks * 2 + lh;          // 16B k-chunk index (0..7)
        uint32_t af[2][2][4];
#pragma unroll
        for (int arr = 0; arr < 2; arr++)
#pragma unroll
            for (int mi = 0; mi < 2; mi++) {
                int r = wm + mi * 16 + lm;
                ldmx4(af[arr][mi], sA + arr * 16384 + r * 128 + ((ch ^ (r & 7)) << 4));
            }
#pragma unroll
        for (int g = 0; g < 2; g++) {
            uint32_t bfr[4][4];
#pragma unroll
            for (int nb = 0; nb < 4; nb++) {
                int r = wn + nb * 16 + lm;
                ldmx4(bfr[nb], sB + g * 16384 + r * 128 + ((ch ^ (r & 7)) << 4));
            }
#pragma unroll
            for (int a = 0; a < 2; a++) {
                if (a < NApg[g]) {
#pragma unroll
                    for (int mi = 0; mi < 2; mi++)
#pragma unroll
                        for (int nb = 0; nb < 4; nb++) {
                            mma_f16(acc[mi][nb * 2 + 0], af[a][mi], bfr[nb][0], bfr[nb][2]);
                            mma_f16(acc[mi][nb * 2 + 1], af[a][mi], bfr[nb][1], bfr[nb][3]);
                        }
                }
            }
        }
    }

    // ---- direct write of block (bi, bj) ----
    const int rl = wm + (lane >> 2);          // local row (of first mi)
    const int cl = wn + (lane & 3) * 2;       // local col
    const int rowb = bi * 128 + rl;
    const int colb = bj * 128 + cl;
#pragma unroll
    for (int mi = 0; mi < 2; mi++) {
#pragma unroll
        for (int jj = 0; jj < 8; jj++) {
            const float* d = acc[mi][jj];
            size_t o0 = (size_t)(rowb + mi * 16) * 16384ull + colb + jj * 8;
            size_t o1 = o0 + 8ull * 16384ull;
            float2 v0 = make_float2(d[0], d[1]);
            float2 v1 = make_float2(d[2], d[3]);
            __stcs(reinterpret_cast<float2*>(padj + o0), v0);
            __stcs(reinterpret_cast<float2*>(padj + o1), v1);
            float2 m0 = make_float2(v0.x > 0.f ? 1.f : 0.f, v0.y > 0.f ? 1.f : 0.f);
            float2 m1 = make_float2(v1.x > 0.f ? 1.f : 0.f, v1.y > 0.f ? 1.f : 0.f);
            __stcs(reinterpret_cast<float2*>(maskp + o0), m0);
            __stcs(reinterpret_cast<float2*>(maskp + o1), m1);
        }
    }

    // ---- mirrored write of block (bj, bi) via smem transpose ----
    if (bi != bj) {
        __syncthreads();
        float* smt = reinterpret_cast<float*>(smem);
#pragma unroll
        for (int mi = 0; mi < 2; mi++) {
#pragma unroll
            for (int jj = 0; jj < 8; jj++) {
                const float* d = acc[mi][jj];
                int r = rl + mi * 16;
                int c = cl + jj * 8;
                smt[(c + 0) * TSTRIDE + r]     = d[0];
                smt[(c + 1) * TSTRIDE + r]     = d[1];
                smt[(c + 0) * TSTRIDE + r + 8] = d[2];
                smt[(c + 1) * TSTRIDE + r + 8] = d[3];
            }
        }
        __syncthreads();
        for (int i = tid; i < 16384; i += 256) {
            int r = i >> 7, c = i & 127;
            float v = smt[r * TSTRIDE + c];
            size_t o = (size_t)(bj * 128 + r) * 16384ull + (size_t)bi * 128 + c;
            __stcs(padj + o, v);
            __stcs(maskp + o, v > 0.f ? 1.f : 0.f);
        }
    }
}

// ============================================================
extern "C" void kernel_launch(void* const* d_in, const int* in_sizes, int n_in,
                              void* d_out, int out_size) {
    const float* x   = (const float*)d_in[0];
    const int*   ei  = (const int*)d_in[1];
    const int*   elb = (const int*)d_in[2];
    const float* Wl1 = (const float*)d_in[3];
    const float* bl1 = (const float*)d_in[4];
    const float* Wr1 = (const float*)d_in[5];
    const float* Wl2 = (const float*)d_in[6];
    const float* bl2 = (const float*)d_in[7];
    const float* Wr2 = (const float*)d_in[8];

    float* out   = (float*)d_out;
    float* sage1 = out + O_SAGE1;
    float* z     = out + O_Z;
    float* dmul  = out + O_DMUL;
    float* dsum  = out + O_DSUM;
    float* padj  = out + O_PADJ;
    float* maskp = out + O_MASK;

    (void)cudaFuncSetAttribute(k_bigmm_mma, cudaFuncAttributeMaxDynamicSharedMemorySize, SMEM_MM);

    k_zero<<<3088, 256>>>();
    k_scatter1<<<65536, 256>>>(x, ei, ei + N_EDGES);
    k_invdeg<<<64, 256>>>();
    k_gemm1<<<256, 256>>>(x, Wl1, Wr1, bl1, sage1);
    k_gemm_pre<<<512, 256>>>(sage1, Wl2);
    k_scatter2<<<32768, 256>>>(ei, ei + N_EDGES);
    k_gemm2<<<512, 256>>>(sage1, Wr2, bl2, z);
    k_split<<<4096, 256>>>(z);
    k_decode<<<16384, 256>>>(z, elb, dmul, dsum);
    k_bigmm_mma<<<8256, 256, SMEM_MM>>>(padj, maskp);
}

// round 14
// speedup vs baseline: 2.4569x; 1.0142x over previous
#include <cuda_runtime.h>
#include <cuda_fp16.h>
#include <cstdint>

typedef unsigned long long ull;

#define N_NODES 16384
#define N_EDGES 524288
#define N_LBL   131072

// ---- output layout (flattened float32 concat in reference-return order) ----
#define O_SAGE1 0ull
#define L_SAGE1 (16384ull*128ull)
#define O_Z     (O_SAGE1 + L_SAGE1)
#define L_Z     (16384ull*64ull)
#define O_DMUL  (O_Z + L_Z)
#define L_DMUL  (131072ull*64ull)
#define O_DSUM  (O_DMUL + L_DMUL)
#define L_DSUM  (131072ull)
#define O_PADJ  (O_DSUM + L_DSUM)
#define L_PADJ  (16384ull*16384ull)
#define O_MASK  (O_PADJ + L_PADJ)

// ---- scratch (device globals; no allocation allowed) ----
__device__ __align__(16) float g_agg1[N_NODES * 128];   // also reused as y1 [N,64]
__device__ __align__(16) float g_agg2[N_NODES * 64];
__device__ __align__(16) float g_deg[N_NODES];
// exact 2-way fp16 split of z: z = h + m (residual ~2^-23 |z|)
__device__ __align__(16) __half g_zh[N_NODES * 64];
__device__ __align__(16) __half g_zm[N_NODES * 64];

// ============================================================
// zero scratch: g_agg1 (524288 f4) + g_agg2 (262144 f4) + deg (4096 f4)
// ============================================================
__global__ void k_zero() {
    unsigned i = blockIdx.x * 256u + threadIdx.x;
    float4 zv = make_float4(0.f, 0.f, 0.f, 0.f);
    if (i < 524288u) {
        reinterpret_cast<float4*>(g_agg1)[i] = zv;
    } else if (i < 786432u) {
        reinterpret_cast<float4*>(g_agg2)[i - 524288u] = zv;
    } else if (i < 790528u) {
        reinterpret_cast<float4*>(g_deg)[i - 786432u] = zv;
    }
}

// ============================================================
// scatter1: one warp per edge, 128 ch, float4 vector atomics
// ============================================================
__global__ void k_scatter1(const float* __restrict__ x,
                           const int* __restrict__ src, const int* __restrict__ dst) {
    unsigned t = blockIdx.x * 256u + threadIdx.x;
    unsigned e = t >> 5, lane = t & 31u;
    if (e >= N_EDGES) return;
    int s = src[e], d = dst[e];
    float4 v = reinterpret_cast<const float4*>(x + (size_t)s * 128)[lane];
    atomicAdd(reinterpret_cast<float4*>(g_agg1 + (size_t)d * 128 + lane * 4), v);
    if (lane == 0) atomicAdd(g_deg + d, 1.0f);
}

// ============================================================
// scatter2: half-warp per edge, 64 ch (y1 = sage1 @ W_l2 pre-applied)
// ============================================================
__global__ void k_scatter2(const int* __restrict__ src, const int* __restrict__ dst) {
    unsigned t = blockIdx.x * 256u + threadIdx.x;
    unsigned e = t >> 4, lane = t & 15u;
    if (e >= N_EDGES) return;
    int s = src[e], d = dst[e];
    float4 v = reinterpret_cast<const float4*>(g_agg1 + (size_t)s * 64)[lane];
    atomicAdd(reinterpret_cast<float4*>(g_agg2 + (size_t)d * 64 + lane * 4), v);
}

// ============================================================
// Layer 1: sage1 = relu( mean1 @ W_l1 + b_l1 + x @ W_r1 )
// Block 64 rows x 128 cols, 256 threads, thread tile 4x8.
// ============================================================
#define YS_STRIDE 68
__global__ void __launch_bounds__(256, 3) k_gemm1(const float* __restrict__ x,
                                                  const float* __restrict__ Wl,
                                                  const float* __restrict__ Wr,
                                                  const float* __restrict__ bias,
                                                  float* __restrict__ out) {
    __shared__ float Ws[64 * 128];
    __shared__ float Ys[64 * YS_STRIDE];
    const int t = threadIdx.x;
    const int row0 = blockIdx.x * 64;
    const int tr = t >> 4, tc = t & 15;

    float acc[4][8];
#pragma unroll
    for (int jj = 0; jj < 8; jj++) {
        float bv = bias[tc * 8 + jj];
#pragma unroll
        for (int ii = 0; ii < 4; ii++) acc[ii][jj] = bv;
    }

    for (int c = 0; c < 4; c++) {
        for (int i = t; i < 2048; i += 256) {
            int l = i >> 5, q = i & 31;
            int g = c * 64 + l;
            float4 v = (g < 128)
                ? reinterpret_cast<const float4*>(Wl + (size_t)g * 128)[q]
                : reinterpret_cast<const float4*>(Wr + (size_t)(g - 128) * 128)[q];
            reinterpret_cast<float4*>(Ws + l * 128)[q] = v;
        }
        for (int i = t; i < 1024; i += 256) {
            int r = i >> 4, q = i & 15;
            int n = row0 + r;
            float4 v;
            if (c < 2) {
                v = reinterpret_cast<const float4*>(g_agg1 + (size_t)n * 128 + c * 64)[q];
                float s = 1.0f / fmaxf(g_deg[n], 1.0f);
                v.x *= s; v.y *= s; v.z *= s; v.w *= s;
            } else {
                v = reinterpret_cast<const float4*>(x + (size_t)n * 128 + (c - 2) * 64)[q];
            }
            reinterpret_cast<float4*>(Ys + r * YS_STRIDE)[q] = v;
        }
        __syncthreads();
#pragma unroll 4
        for (int k = 0; k < 64; k++) {
            float a[4];
#pragma unroll
            for (int ii = 0; ii < 4; ii++) a[ii] = Ys[(4 * tr + ii) * YS_STRIDE + k];
            float w[8];
            *reinterpret_cast<float4*>(w)     = *reinterpret_cast<const float4*>(Ws + k * 128 + tc * 8);
            *reinterpret_cast<float4*>(w + 4) = *reinterpret_cast<const float4*>(Ws + k * 128 + tc * 8 + 4);
#pragma unroll
            for (int ii = 0; ii < 4; ii++)
#pragma unroll
                for (int jj = 0; jj < 8; jj++) acc[ii][jj] = fmaf(a[ii], w[jj], acc[ii][jj]);
        }
        __syncthreads();
    }
#pragma unroll
    for (int ii = 0; ii < 4; ii++) {
        size_t off = (size_t)(row0 + 4 * tr + ii) * 128 + tc * 8;
        float4 v0 = make_float4(fmaxf(acc[ii][0], 0.f), fmaxf(acc[ii][1], 0.f),
                                fmaxf(acc[ii][2], 0.f), fmaxf(acc[ii][3], 0.f));
        float4 v1 = make_float4(fmaxf(acc[ii][4], 0.f), fmaxf(acc[ii][5], 0.f),
                                fmaxf(acc[ii][6], 0.f), fmaxf(acc[ii][7], 0.f));
        *reinterpret_cast<float4*>(out + off)     = v0;
        *reinterpret_cast<float4*>(out + off + 4) = v1;
    }
}

// ============================================================
// gemm_pre: y1 = sage1 @ W_l2  ([N,128]@[128,64] -> g_agg1 as [N,64])
// ============================================================
__global__ void __launch_bounds__(256) k_gemm_pre(const float* __restrict__ sage1,
                                                  const float* __restrict__ Wl) {
    __shared__ float Ws[64 * 64];
    __shared__ float Ys[32 * YS_STRIDE];
    const int t = threadIdx.x;
    const int row0 = blockIdx.x * 32;
    const int tr = t >> 3, tc = t & 7;

    float acc[8];
#pragma unroll
    for (int jj = 0; jj < 8; jj++) acc[jj] = 0.f;

    for (int c = 0; c < 2; c++) {
        for (int i = t; i < 1024; i += 256) {
            int l = i >> 4, q = i & 15;
            reinterpret_cast<float4*>(Ws + l * 64)[q] =
                reinterpret_cast<const float4*>(Wl + (size_t)(c * 64 + l) * 64)[q];
        }
        for (int i = t; i < 512; i += 256) {
            int r = i >> 4, q = i & 15;
            reinterpret_cast<float4*>(Ys + r * YS_STRIDE)[q] =
                reinterpret_cast<const float4*>(sage1 + (size_t)(row0 + r) * 128 + c * 64)[q];
        }
        __syncthreads();
#pragma unroll 8
        for (int k = 0; k < 64; k++) {
            float a = Ys[tr * YS_STRIDE + k];
            float w[8];
            *reinterpret_cast<float4*>(w)     = *reinterpret_cast<const float4*>(Ws + k * 64 + tc * 8);
            *reinterpret_cast<float4*>(w + 4) = *reinterpret_cast<const float4*>(Ws + k * 64 + tc * 8 + 4);
#pragma unroll
            for (int jj = 0; jj < 8; jj++) acc[jj] = fmaf(a, w[jj], acc[jj]);
        }
        __syncthreads();
    }
    size_t off = (size_t)(row0 + tr) * 64 + tc * 8;
    *reinterpret_cast<float4*>(g_agg1 + off)     = make_float4(acc[0], acc[1], acc[2], acc[3]);
    *reinterpret_cast<float4*>(g_agg1 + off + 4) = make_float4(acc[4], acc[5], acc[6], acc[7]);
}

// ============================================================
// Layer 2: z = mean(y1-agg) + b_l2 + sage1 @ W_r2  (K=128)
// Epilogue also emits the exact fp16 split z = h + m (fused k_split).
// ============================================================
__global__ void __launch_bounds__(256) k_gemm2(const float* __restrict__ sage1,
                                               const float* __restrict__ Wr,
                                               const float* __restrict__ bias,
                                               float* __restrict__ out) {
    __shared__ float Ws[64 * 64];
    __shared__ float Ys[32 * YS_STRIDE];
    const int t = threadIdx.x;
    const int row0 = blockIdx.x * 32;
    const int tr = t >> 3, tc = t & 7;

    const int n = row0 + tr;
    const float sdeg = 1.0f / fmaxf(g_deg[n], 1.0f);
    float acc[8];
    {
        float4 a0 = reinterpret_cast<const float4*>(g_agg2 + (size_t)n * 64 + tc * 8)[0];
        float4 a1 = reinterpret_cast<const float4*>(g_agg2 + (size_t)n * 64 + tc * 8)[1];
        acc[0] = bias[tc * 8 + 0] + sdeg * a0.x;
        acc[1] = bias[tc * 8 + 1] + sdeg * a0.y;
        acc[2] = bias[tc * 8 + 2] + sdeg * a0.z;
        acc[3] = bias[tc * 8 + 3] + sdeg * a0.w;
        acc[4] = bias[tc * 8 + 4] + sdeg * a1.x;
        acc[5] = bias[tc * 8 + 5] + sdeg * a1.y;
        acc[6] = bias[tc * 8 + 6] + sdeg * a1.z;
        acc[7] = bias[tc * 8 + 7] + sdeg * a1.w;
    }

    for (int c = 0; c < 2; c++) {
        for (int i = t; i < 1024; i += 256) {
            int l = i >> 4, q = i & 15;
            reinterpret_cast<float4*>(Ws + l * 64)[q] =
                reinterpret_cast<const float4*>(Wr + (size_t)(c * 64 + l) * 64)[q];
        }
        for (int i = t; i < 512; i += 256) {
            int r = i >> 4, q = i & 15;
            reinterpret_cast<float4*>(Ys + r * YS_STRIDE)[q] =
                reinterpret_cast<const float4*>(sage1 + (size_t)(row0 + r) * 128 + c * 64)[q];
        }
        __syncthreads();
#pragma unroll 8
        for (int k = 0; k < 64; k++) {
            float a = Ys[tr * YS_STRIDE + k];
            float w[8];
            *reinterpret_cast<float4*>(w)     = *reinterpret_cast<const float4*>(Ws + k * 64 + tc * 8);
            *reinterpret_cast<float4*>(w + 4) = *reinterpret_cast<const float4*>(Ws + k * 64 + tc * 8 + 4);
#pragma unroll
            for (int jj = 0; jj < 8; jj++) acc[jj] = fmaf(a, w[jj], acc[jj]);
        }
        __syncthreads();
    }
    size_t off = (size_t)n * 64 + tc * 8;
    *reinterpret_cast<float4*>(out + off)     = make_float4(acc[0], acc[1], acc[2], acc[3]);
    *reinterpret_cast<float4*>(out + off + 4) = make_float4(acc[4], acc[5], acc[6], acc[7]);

    // fused exact fp16 split: z = h + m
    __align__(16) __half hs[8];
    __align__(16) __half ms[8];
#pragma unroll
    for (int jj = 0; jj < 8; jj++) {
        float v = acc[jj];
        __half h = __float2half_rn(v);
        float r1 = v - __half2float(h);
        __half m = __float2half_rn(r1);
        hs[jj] = h; ms[jj] = m;
    }
    *reinterpret_cast<uint4*>(g_zh + off) = *reinterpret_cast<uint4*>(hs);
    *reinterpret_cast<uint4*>(g_zm + off) = *reinterpret_cast<uint4*>(ms);
}

// ============================================================
// decode: one warp per label edge
// ============================================================
__global__ void k_decode(const float* __restrict__ z, const int* __restrict__ elbl,
                         float* __restrict__ dmul, float* __restrict__ dsum) {
    unsigned t = blockIdx.x * 256u + threadIdx.x;
    unsigned e = t >> 5, lane = t & 31u;
    if (e >= N_LBL) return;
    int a = elbl[e], b = elbl[N_LBL + e];
    float2 za = reinterpret_cast<const float2*>(z + (size_t)a * 64)[lane];
    float2 zb = reinterpret_cast<const float2*>(z + (size_t)b * 64)[lane];
    float2 m = make_float2(za.x * zb.x, za.y * zb.y);
    reinterpret_cast<float2*>(dmul + (size_t)e * 64)[lane] = m;
    float s = m.x + m.y;
#pragma unroll
    for (int o = 16; o > 0; o >>= 1) s += __shfl_xor_sync(0xffffffffu, s, o);
    if (lane == 0) dsum[e] = s;
}

// ============================================================
// mma.sync helpers (plain PTX, valid on non-'a' sm_103 target)
// ============================================================
__device__ __forceinline__ uint32_t smem_u32(const void* p) {
    uint32_t a;
    asm("{ .reg .u64 t; cvta.to.shared.u64 t, %1; cvt.u32.u64 %0, t; }" : "=r"(a) : "l"(p));
    return a;
}
__device__ __forceinline__ void ldmx4(uint32_t* r, uint32_t addr) {
    asm volatile("ldmatrix.sync.aligned.m8n8.x4.shared.b16 {%0,%1,%2,%3}, [%4];"
                 : "=r"(r[0]), "=r"(r[1]), "=r"(r[2]), "=r"(r[3]) : "r"(addr));
}
__device__ __forceinline__ void mma_f16(float* d, const uint32_t* a, uint32_t b0, uint32_t b1) {
    asm volatile("mma.sync.aligned.m16n8k16.row.col.f32.f16.f16.f32 "
                 "{%0,%1,%2,%3}, {%4,%5,%6,%7}, {%8,%9}, {%0,%1,%2,%3};"
                 : "+f"(d[0]), "+f"(d[1]), "+f"(d[2]), "+f"(d[3])
                 : "r"(a[0]), "r"(a[1]), "r"(a[2]), "r"(a[3]), "r"(b0), "r"(b1));
}

// ============================================================
// big GEMM (SYMMETRIC + fp16 2-split): prob_adj = z @ z^T.
// Products: hh, mh (B=h group) and hm (B=m group) — dropped terms ~2^-23 rel.
// Lower-triangular CTA tiles only; mirror written via smem transpose (f4 I/O).
// ============================================================
#define SMEM_MM 69632
#define TSTRIDE 132

__global__ void __launch_bounds__(256, 2) k_bigmm_mma(float* __restrict__ padj,
                                                      float* __restrict__ maskp) {
    extern __shared__ char smem[];
    const uint32_t sA = smem_u32(smem);
    const uint32_t sB = sA + 32768;
    const int tid = threadIdx.x;
    const int wid = tid >> 5, lane = tid & 31;

    // triangular decode: blockIdx.x -> (bi, bj), bj <= bi
    int t = blockIdx.x;
    int bi = (int)((sqrtf(8.f * (float)t + 1.f) - 1.f) * 0.5f);
    while ((bi + 1) * (bi + 2) / 2 <= t) bi++;
    while (bi * (bi + 1) / 2 > t) bi--;
    int bj = t - bi * (bi + 1) / 2;

    // ---- fill A tiles: 2 arrays x 128 rows x 8 x 16B chunks ----
    for (int i = tid; i < 2048; i += 256) {
        int arr = i >> 10, rem = i & 1023;
        int r = rem >> 3, c = rem & 7;
        const __half* src = (arr == 0) ? g_zh : g_zm;
        uint4 v = reinterpret_cast<const uint4*>(src + (size_t)(bi * 128 + r) * 64)[c];
        *reinterpret_cast<uint4*>(smem + arr * 16384 + r * 128 + ((c ^ (r & 7)) << 4)) = v;
    }
    // ---- fill B tiles ----
    for (int i = tid; i < 2048; i += 256) {
        int arr = i >> 10, rem = i & 1023;
        int r = rem >> 3, c = rem & 7;
        const __half* src = (arr == 0) ? g_zh : g_zm;
        uint4 v = reinterpret_cast<const uint4*>(src + (size_t)(bj * 128 + r) * 64)[c];
        *reinterpret_cast<uint4*>(smem + 32768 + arr * 16384 + r * 128 + ((c ^ (r & 7)) << 4)) = v;
    }
    __syncthreads();

    const int wm = (wid & 3) * 32;   // warp M offset
    const int wn = (wid >> 2) * 64;  // warp N offset
    const int lm = lane & 15, lh = lane >> 4;

    float acc[2][8][4];
#pragma unroll
    for (int mi = 0; mi < 2; mi++)
#pragma unroll
        for (int jj = 0; jj < 8; jj++)
#pragma unroll
            for (int q = 0; q < 4; q++) acc[mi][jj][q] = 0.f;

    // B=h group (g=0): A in {h, m}; B=m group (g=1): A in {h}
    const int NApg[2] = {2, 1};

#pragma unroll
    for (int ks = 0; ks < 4; ks++) {
        const int ch = ks * 2 + lh;          // 16B k-chunk index (0..7)
        uint32_t af[2][2][4];
#pragma unroll
        for (int arr = 0; arr < 2; arr++)
#pragma unroll
            for (int mi = 0; mi < 2; mi++) {
                int r = wm + mi * 16 + lm;
                ldmx4(af[arr][mi], sA + arr * 16384 + r * 128 + ((ch ^ (r & 7)) << 4));
            }
#pragma unroll
        for (int g = 0; g < 2; g++) {
            uint32_t bfr[4][4];
#pragma unroll
            for (int nb = 0; nb < 4; nb++) {
                int r = wn + nb * 16 + lm;
                ldmx4(bfr[nb], sB + g * 16384 + r * 128 + ((ch ^ (r & 7)) << 4));
            }
#pragma unroll
            for (int a = 0; a < 2; a++) {
                if (a < NApg[g]) {
#pragma unroll
                    for (int mi = 0; mi < 2; mi++)
#pragma unroll
                        for (int nb = 0; nb < 4; nb++) {
                            mma_f16(acc[mi][nb * 2 + 0], af[a][mi], bfr[nb][0], bfr[nb][2]);
                            mma_f16(acc[mi][nb * 2 + 1], af[a][mi], bfr[nb][1], bfr[nb][3]);
                        }
                }
            }
        }
    }

    // ---- direct write of block (bi, bj) ----
    const int rl = wm + (lane >> 2);          // local row (of first mi)
    const int cl = wn + (lane & 3) * 2;       // local col
    const int rowb = bi * 128 + rl;
    const int colb = bj * 128 + cl;
#pragma unroll
    for (int mi = 0; mi < 2; mi++) {
#pragma unroll
        for (int jj = 0; jj < 8; jj++) {
            const float* d = acc[mi][jj];
            size_t o0 = (size_t)(rowb + mi * 16) * 16384ull + colb + jj * 8;
            size_t o1 = o0 + 8ull * 16384ull;
            float2 v0 = make_float2(d[0], d[1]);
            float2 v1 = make_float2(d[2], d[3]);
            __stcs(reinterpret_cast<float2*>(padj + o0), v0);
            __stcs(reinterpret_cast<float2*>(padj + o1), v1);
            float2 m0 = make_float2(v0.x > 0.f ? 1.f : 0.f, v0.y > 0.f ? 1.f : 0.f);
            float2 m1 = make_float2(v1.x > 0.f ? 1.f : 0.f, v1.y > 0.f ? 1.f : 0.f);
            __stcs(reinterpret_cast<float2*>(maskp + o0), m0);
            __stcs(reinterpret_cast<float2*>(maskp + o1), m1);
        }
    }

    // ---- mirrored write of block (bj, bi) via smem transpose ----
    if (bi != bj) {
        __syncthreads();
        float* smt = reinterpret_cast<float*>(smem);
#pragma unroll
        for (int mi = 0; mi < 2; mi++) {
#pragma unroll
            for (int jj = 0; jj < 8; jj++) {
                const float* d = acc[mi][jj];
                int r = rl + mi * 16;
                int c = cl + jj * 8;
                smt[(c + 0) * TSTRIDE + r]     = d[0];
                smt[(c + 1) * TSTRIDE + r]     = d[1];
                smt[(c + 0) * TSTRIDE + r + 8] = d[2];
                smt[(c + 1) * TSTRIDE + r + 8] = d[3];
            }
        }
        __syncthreads();
        // float4 write-out: one warp covers one 512B row segment
        for (int i = tid; i < 4096; i += 256) {
            int r = i >> 5, c4 = (i & 31) * 4;
            float4 v = *reinterpret_cast<const float4*>(smt + r * TSTRIDE + c4);
            size_t o = (size_t)(bj * 128 + r) * 16384ull + (size_t)bi * 128 + c4;
            __stcs(reinterpret_cast<float4*>(padj + o), v);
            float4 mk = make_float4(v.x > 0.f ? 1.f : 0.f, v.y > 0.f ? 1.f : 0.f,
                                    v.z > 0.f ? 1.f : 0.f, v.w > 0.f ? 1.f : 0.f);
            __stcs(reinterpret_cast<float4*>(maskp + o), mk);
        }
    }
}

// ============================================================
extern "C" void kernel_launch(void* const* d_in, const int* in_sizes, int n_in,
                              void* d_out, int out_size) {
    const float* x   = (const float*)d_in[0];
    const int*   ei  = (const int*)d_in[1];
    const int*   elb = (const int*)d_in[2];
    const float* Wl1 = (const float*)d_in[3];
    const float* bl1 = (const float*)d_in[4];
    const float* Wr1 = (const float*)d_in[5];
    const float* Wl2 = (const float*)d_in[6];
    const float* bl2 = (const float*)d_in[7];
    const float* Wr2 = (const float*)d_in[8];

    float* out   = (float*)d_out;
    float* sage1 = out + O_SAGE1;
    float* z     = out + O_Z;
    float* dmul  = out + O_DMUL;
    float* dsum  = out + O_DSUM;
    float* padj  = out + O_PADJ;
    float* maskp = out + O_MASK;

    (void)cudaFuncSetAttribute(k_bigmm_mma, cudaFuncAttributeMaxDynamicSharedMemorySize, SMEM_MM);

    k_zero<<<3088, 256>>>();
    k_scatter1<<<65536, 256>>>(x, ei, ei + N_EDGES);
    k_gemm1<<<256, 256>>>(x, Wl1, Wr1, bl1, sage1);
    k_gemm_pre<<<512, 256>>>(sage1, Wl2);
    k_scatter2<<<32768, 256>>>(ei, ei + N_EDGES);
    k_gemm2<<<512, 256>>>(sage1, Wr2, bl2, z);
    k_decode<<<16384, 256>>>(z, elb, dmul, dsum);
    k_bigmm_mma<<<8256, 256, SMEM_MM>>>(padj, maskp);
}

// round 15
// speedup vs baseline: 2.5728x; 1.0472x over previous
#include <cuda_runtime.h>
#include <cuda_fp16.h>
#include <cstdint>

typedef unsigned long long ull;

#define N_NODES 16384
#define N_EDGES 524288
#define N_LBL   131072

// ---- output layout (flattened float32 concat in reference-return order) ----
#define O_SAGE1 0ull
#define L_SAGE1 (16384ull*128ull)
#define O_Z     (O_SAGE1 + L_SAGE1)
#define L_Z     (16384ull*64ull)
#define O_DMUL  (O_Z + L_Z)
#define L_DMUL  (131072ull*64ull)
#define O_DSUM  (O_DMUL + L_DMUL)
#define L_DSUM  (131072ull)
#define O_PADJ  (O_DSUM + L_DSUM)
#define L_PADJ  (16384ull*16384ull)
#define O_MASK  (O_PADJ + L_PADJ)

// ---- scratch (device globals; no allocation allowed) ----
__device__ __align__(16) float g_agg1[N_NODES * 128];   // also reused as y1 [N,64]
__device__ __align__(16) float g_agg2[N_NODES * 64];
__device__ __align__(16) float g_deg[N_NODES];
// exact 2-way fp16 split of z: z = h + m (residual ~2^-23 |z|)
__device__ __align__(16) __half g_zh[N_NODES * 64];
__device__ __align__(16) __half g_zm[N_NODES * 64];

// ============================================================
// zero scratch: g_agg1 (524288 f4) + g_agg2 (262144 f4) + deg (4096 f4)
// ============================================================
__global__ void k_zero() {
    unsigned i = blockIdx.x * 256u + threadIdx.x;
    float4 zv = make_float4(0.f, 0.f, 0.f, 0.f);
    if (i < 524288u) {
        reinterpret_cast<float4*>(g_agg1)[i] = zv;
    } else if (i < 786432u) {
        reinterpret_cast<float4*>(g_agg2)[i - 524288u] = zv;
    } else if (i < 790528u) {
        reinterpret_cast<float4*>(g_deg)[i - 786432u] = zv;
    }
}

// ============================================================
// scatter1: one warp per edge, 128 ch, float4 vector atomics
// ============================================================
__global__ void k_scatter1(const float* __restrict__ x,
                           const int* __restrict__ src, const int* __restrict__ dst) {
    unsigned t = blockIdx.x * 256u + threadIdx.x;
    unsigned e = t >> 5, lane = t & 31u;
    if (e >= N_EDGES) return;
    int s = src[e], d = dst[e];
    float4 v = reinterpret_cast<const float4*>(x + (size_t)s * 128)[lane];
    atomicAdd(reinterpret_cast<float4*>(g_agg1 + (size_t)d * 128 + lane * 4), v);
    if (lane == 0) atomicAdd(g_deg + d, 1.0f);
}

// ============================================================
// scatter2: half-warp per edge, 64 ch (y1 = sage1 @ W_l2 pre-applied)
// ============================================================
__global__ void k_scatter2(const int* __restrict__ src, const int* __restrict__ dst) {
    unsigned t = blockIdx.x * 256u + threadIdx.x;
    unsigned e = t >> 4, lane = t & 15u;
    if (e >= N_EDGES) return;
    int s = src[e], d = dst[e];
    float4 v = reinterpret_cast<const float4*>(g_agg1 + (size_t)s * 64)[lane];
    atomicAdd(reinterpret_cast<float4*>(g_agg2 + (size_t)d * 64 + lane * 4), v);
}

// ============================================================
// Layer 1: sage1 = relu( mean1 @ W_l1 + b_l1 + x @ W_r1 )
// Block 64 rows x 128 cols, 256 threads, thread tile 4x8.
// ============================================================
#define YS_STRIDE 68
__global__ void __launch_bounds__(256, 3) k_gemm1(const float* __restrict__ x,
                                                  const float* __restrict__ Wl,
                                                  const float* __restrict__ Wr,
                                                  const float* __restrict__ bias,
                                                  float* __restrict__ out) {
    __shared__ float Ws[64 * 128];
    __shared__ float Ys[64 * YS_STRIDE];
    const int t = threadIdx.x;
    const int row0 = blockIdx.x * 64;
    const int tr = t >> 4, tc = t & 15;

    float acc[4][8];
#pragma unroll
    for (int jj = 0; jj < 8; jj++) {
        float bv = bias[tc * 8 + jj];
#pragma unroll
        for (int ii = 0; ii < 4; ii++) acc[ii][jj] = bv;
    }

    for (int c = 0; c < 4; c++) {
        for (int i = t; i < 2048; i += 256) {
            int l = i >> 5, q = i & 31;
            int g = c * 64 + l;
            float4 v = (g < 128)
                ? reinterpret_cast<const float4*>(Wl + (size_t)g * 128)[q]
                : reinterpret_cast<const float4*>(Wr + (size_t)(g - 128) * 128)[q];
            reinterpret_cast<float4*>(Ws + l * 128)[q] = v;
        }
        for (int i = t; i < 1024; i += 256) {
            int r = i >> 4, q = i & 15;
            int n = row0 + r;
            float4 v;
            if (c < 2) {
                v = reinterpret_cast<const float4*>(g_agg1 + (size_t)n * 128 + c * 64)[q];
                float s = 1.0f / fmaxf(g_deg[n], 1.0f);
                v.x *= s; v.y *= s; v.z *= s; v.w *= s;
            } else {
                v = reinterpret_cast<const float4*>(x + (size_t)n * 128 + (c - 2) * 64)[q];
            }
            reinterpret_cast<float4*>(Ys + r * YS_STRIDE)[q] = v;
        }
        __syncthreads();
#pragma unroll 4
        for (int k = 0; k < 64; k++) {
            float a[4];
#pragma unroll
            for (int ii = 0; ii < 4; ii++) a[ii] = Ys[(4 * tr + ii) * YS_STRIDE + k];
            float w[8];
            *reinterpret_cast<float4*>(w)     = *reinterpret_cast<const float4*>(Ws + k * 128 + tc * 8);
            *reinterpret_cast<float4*>(w + 4) = *reinterpret_cast<const float4*>(Ws + k * 128 + tc * 8 + 4);
#pragma unroll
            for (int ii = 0; ii < 4; ii++)
#pragma unroll
                for (int jj = 0; jj < 8; jj++) acc[ii][jj] = fmaf(a[ii], w[jj], acc[ii][jj]);
        }
        __syncthreads();
    }
#pragma unroll
    for (int ii = 0; ii < 4; ii++) {
        size_t off = (size_t)(row0 + 4 * tr + ii) * 128 + tc * 8;
        float4 v0 = make_float4(fmaxf(acc[ii][0], 0.f), fmaxf(acc[ii][1], 0.f),
                                fmaxf(acc[ii][2], 0.f), fmaxf(acc[ii][3], 0.f));
        float4 v1 = make_float4(fmaxf(acc[ii][4], 0.f), fmaxf(acc[ii][5], 0.f),
                                fmaxf(acc[ii][6], 0.f), fmaxf(acc[ii][7], 0.f));
        *reinterpret_cast<float4*>(out + off)     = v0;
        *reinterpret_cast<float4*>(out + off + 4) = v1;
    }
}

// ============================================================
// gemm_pre: y1 = sage1 @ W_l2  ([N,128]@[128,64] -> g_agg1 as [N,64])
// Block 64 rows x 64 cols, 256 threads, thread tile 2x8.
// ============================================================
__global__ void __launch_bounds__(256) k_gemm_pre(const float* __restrict__ sage1,
                                                  const float* __restrict__ Wl) {
    __shared__ float Ws[64 * 64];
    __shared__ float Ys[64 * YS_STRIDE];
    const int t = threadIdx.x;
    const int row0 = blockIdx.x * 64;
    const int tr = t >> 3, tc = t & 7;

    float acc[2][8];
#pragma unroll
    for (int ii = 0; ii < 2; ii++)
#pragma unroll
        for (int jj = 0; jj < 8; jj++) acc[ii][jj] = 0.f;

    for (int c = 0; c < 2; c++) {
        for (int i = t; i < 1024; i += 256) {
            int l = i >> 4, q = i & 15;
            reinterpret_cast<float4*>(Ws + l * 64)[q] =
                reinterpret_cast<const float4*>(Wl + (size_t)(c * 64 + l) * 64)[q];
        }
        for (int i = t; i < 1024; i += 256) {
            int r = i >> 4, q = i & 15;
            reinterpret_cast<float4*>(Ys + r * YS_STRIDE)[q] =
                reinterpret_cast<const float4*>(sage1 + (size_t)(row0 + r) * 128 + c * 64)[q];
        }
        __syncthreads();
#pragma unroll 8
        for (int k = 0; k < 64; k++) {
            float a0 = Ys[(2 * tr) * YS_STRIDE + k];
            float a1 = Ys[(2 * tr + 1) * YS_STRIDE + k];
            float w[8];
            *reinterpret_cast<float4*>(w)     = *reinterpret_cast<const float4*>(Ws + k * 64 + tc * 8);
            *reinterpret_cast<float4*>(w + 4) = *reinterpret_cast<const float4*>(Ws + k * 64 + tc * 8 + 4);
#pragma unroll
            for (int jj = 0; jj < 8; jj++) {
                acc[0][jj] = fmaf(a0, w[jj], acc[0][jj]);
                acc[1][jj] = fmaf(a1, w[jj], acc[1][jj]);
            }
        }
        __syncthreads();
    }
#pragma unroll
    for (int ii = 0; ii < 2; ii++) {
        size_t off = (size_t)(row0 + 2 * tr + ii) * 64 + tc * 8;
        *reinterpret_cast<float4*>(g_agg1 + off)     = make_float4(acc[ii][0], acc[ii][1], acc[ii][2], acc[ii][3]);
        *reinterpret_cast<float4*>(g_agg1 + off + 4) = make_float4(acc[ii][4], acc[ii][5], acc[ii][6], acc[ii][7]);
    }
}

// ============================================================
// Layer 2: z = mean(y1-agg) + b_l2 + sage1 @ W_r2  (K=128)
// Block 64 rows x 64 cols, thread tile 2x8. Fused fp16 split epilogue.
// ============================================================
__global__ void __launch_bounds__(256) k_gemm2(const float* __restrict__ sage1,
                                               const float* __restrict__ Wr,
                                               const float* __restrict__ bias,
                                               float* __restrict__ out) {
    __shared__ float Ws[64 * 64];
    __shared__ float Ys[64 * YS_STRIDE];
    const int t = threadIdx.x;
    const int row0 = blockIdx.x * 64;
    const int tr = t >> 3, tc = t & 7;

    float acc[2][8];
#pragma unroll
    for (int ii = 0; ii < 2; ii++) {
        const int n = row0 + 2 * tr + ii;
        const float sdeg = 1.0f / fmaxf(g_deg[n], 1.0f);
        float4 a0 = reinterpret_cast<const float4*>(g_agg2 + (size_t)n * 64 + tc * 8)[0];
        float4 a1 = reinterpret_cast<const float4*>(g_agg2 + (size_t)n * 64 + tc * 8)[1];
        acc[ii][0] = bias[tc * 8 + 0] + sdeg * a0.x;
        acc[ii][1] = bias[tc * 8 + 1] + sdeg * a0.y;
        acc[ii][2] = bias[tc * 8 + 2] + sdeg * a0.z;
        acc[ii][3] = bias[tc * 8 + 3] + sdeg * a0.w;
        acc[ii][4] = bias[tc * 8 + 4] + sdeg * a1.x;
        acc[ii][5] = bias[tc * 8 + 5] + sdeg * a1.y;
        acc[ii][6] = bias[tc * 8 + 6] + sdeg * a1.z;
        acc[ii][7] = bias[tc * 8 + 7] + sdeg * a1.w;
    }

    for (int c = 0; c < 2; c++) {
        for (int i = t; i < 1024; i += 256) {
            int l = i >> 4, q = i & 15;
            reinterpret_cast<float4*>(Ws + l * 64)[q] =
                reinterpret_cast<const float4*>(Wr + (size_t)(c * 64 + l) * 64)[q];
        }
        for (int i = t; i < 1024; i += 256) {
            int r = i >> 4, q = i & 15;
            reinterpret_cast<float4*>(Ys + r * YS_STRIDE)[q] =
                reinterpret_cast<const float4*>(sage1 + (size_t)(row0 + r) * 128 + c * 64)[q];
        }
        __syncthreads();
#pragma unroll 8
        for (int k = 0; k < 64; k++) {
            float a0 = Ys[(2 * tr) * YS_STRIDE + k];
            float a1 = Ys[(2 * tr + 1) * YS_STRIDE + k];
            float w[8];
            *reinterpret_cast<float4*>(w)     = *reinterpret_cast<const float4*>(Ws + k * 64 + tc * 8);
            *reinterpret_cast<float4*>(w + 4) = *reinterpret_cast<const float4*>(Ws + k * 64 + tc * 8 + 4);
#pragma unroll
            for (int jj = 0; jj < 8; jj++) {
                acc[0][jj] = fmaf(a0, w[jj], acc[0][jj]);
                acc[1][jj] = fmaf(a1, w[jj], acc[1][jj]);
            }
        }
        __syncthreads();
    }
#pragma unroll
    for (int ii = 0; ii < 2; ii++) {
        size_t off = (size_t)(row0 + 2 * tr + ii) * 64 + tc * 8;
        *reinterpret_cast<float4*>(out + off)     = make_float4(acc[ii][0], acc[ii][1], acc[ii][2], acc[ii][3]);
        *reinterpret_cast<float4*>(out + off + 4) = make_float4(acc[ii][4], acc[ii][5], acc[ii][6], acc[ii][7]);

        // fused exact fp16 split: z = h + m
        __align__(16) __half hs[8];
        __align__(16) __half ms[8];
#pragma unroll
        for (int jj = 0; jj < 8; jj++) {
            float v = acc[ii][jj];
            __half h = __float2half_rn(v);
            float r1 = v - __half2float(h);
            __half m = __float2half_rn(r1);
            hs[jj] = h; ms[jj] = m;
        }
        *reinterpret_cast<uint4*>(g_zh + off) = *reinterpret_cast<uint4*>(hs);
        *reinterpret_cast<uint4*>(g_zm + off) = *reinterpret_cast<uint4*>(ms);
    }
}

// ============================================================
// decode: one warp per label edge
// ============================================================
__global__ void k_decode(const float* __restrict__ z, const int* __restrict__ elbl,
                         float* __restrict__ dmul, float* __restrict__ dsum) {
    unsigned t = blockIdx.x * 256u + threadIdx.x;
    unsigned e = t >> 5, lane = t & 31u;
    if (e >= N_LBL) return;
    int a = elbl[e], b = elbl[N_LBL + e];
    float2 za = reinterpret_cast<const float2*>(z + (size_t)a * 64)[lane];
    float2 zb = reinterpret_cast<const float2*>(z + (size_t)b * 64)[lane];
    float2 m = make_float2(za.x * zb.x, za.y * zb.y);
    reinterpret_cast<float2*>(dmul + (size_t)e * 64)[lane] = m;
    float s = m.x + m.y;
#pragma unroll
    for (int o = 16; o > 0; o >>= 1) s += __shfl_xor_sync(0xffffffffu, s, o);
    if (lane == 0) dsum[e] = s;
}

// ============================================================
// mma.sync helpers (plain PTX, valid on non-'a' sm_103 target)
// ============================================================
__device__ __forceinline__ uint32_t smem_u32(const void* p) {
    uint32_t a;
    asm("{ .reg .u64 t; cvta.to.shared.u64 t, %1; cvt.u32.u64 %0, t; }" : "=r"(a) : "l"(p));
    return a;
}
__device__ __forceinline__ void ldmx4(uint32_t* r, uint32_t addr) {
    asm volatile("ldmatrix.sync.aligned.m8n8.x4.shared.b16 {%0,%1,%2,%3}, [%4];"
                 : "=r"(r[0]), "=r"(r[1]), "=r"(r[2]), "=r"(r[3]) : "r"(addr));
}
__device__ __forceinline__ void mma_f16(float* d, const uint32_t* a, uint32_t b0, uint32_t b1) {
    asm volatile("mma.sync.aligned.m16n8k16.row.col.f32.f16.f16.f32 "
                 "{%0,%1,%2,%3}, {%4,%5,%6,%7}, {%8,%9}, {%0,%1,%2,%3};"
                 : "+f"(d[0]), "+f"(d[1]), "+f"(d[2]), "+f"(d[3])
                 : "r"(a[0]), "r"(a[1]), "r"(a[2]), "r"(a[3]), "r"(b0), "r"(b1));
}

// ============================================================
// big GEMM (SYMMETRIC + fp16 2-split): prob_adj = z @ z^T.
// Products: hh, mh (B=h group) and hm (B=m group) — dropped terms ~2^-23 rel.
// Lower-triangular CTA tiles only; mirror written via smem transpose (f4 I/O).
// ============================================================
#define SMEM_MM 69632
#define TSTRIDE 132

__global__ void __launch_bounds__(256, 2) k_bigmm_mma(float* __restrict__ padj,
                                                      float* __restrict__ maskp) {
    extern __shared__ char smem[];
    const uint32_t sA = smem_u32(smem);
    const uint32_t sB = sA + 32768;
    const int tid = threadIdx.x;
    const int wid = tid >> 5, lane = tid & 31;

    // triangular decode: blockIdx.x -> (bi, bj), bj <= bi
    int t = blockIdx.x;
    int bi = (int)((sqrtf(8.f * (float)t + 1.f) - 1.f) * 0.5f);
    while ((bi + 1) * (bi + 2) / 2 <= t) bi++;
    while (bi * (bi + 1) / 2 > t) bi--;
    int bj = t - bi * (bi + 1) / 2;

    // ---- fill A tiles: 2 arrays x 128 rows x 8 x 16B chunks ----
    for (int i = tid; i < 2048; i += 256) {
        int arr = i >> 10, rem = i & 1023;
        int r = rem >> 3, c = rem & 7;
        const __half* src = (arr == 0) ? g_zh : g_zm;
        uint4 v = reinterpret_cast<const uint4*>(src + (size_t)(bi * 128 + r) * 64)[c];
        *reinterpret_cast<uint4*>(smem + arr * 16384 + r * 128 + ((c ^ (r & 7)) << 4)) = v;
    }
    // ---- fill B tiles ----
    for (int i = tid; i < 2048; i += 256) {
        int arr = i >> 10, rem = i & 1023;
        int r = rem >> 3, c = rem & 7;
        const __half* src = (arr == 0) ? g_zh : g_zm;
        uint4 v = reinterpret_cast<const uint4*>(src + (size_t)(bj * 128 + r) * 64)[c];
        *reinterpret_cast<uint4*>(smem + 32768 + arr * 16384 + r * 128 + ((c ^ (r & 7)) << 4)) = v;
    }
    __syncthreads();

    const int wm = (wid & 3) * 32;   // warp M offset
    const int wn = (wid >> 2) * 64;  // warp N offset
    const int lm = lane & 15, lh = lane >> 4;

    float acc[2][8][4];
#pragma unroll
    for (int mi = 0; mi < 2; mi++)
#pragma unroll
        for (int jj = 0; jj < 8; jj++)
#pragma unroll
            for (int q = 0; q < 4; q++) acc[mi][jj][q] = 0.f;

    // B=h group (g=0): A in {h, m}; B=m group (g=1): A in {h}
    const int NApg[2] = {2, 1};

#pragma unroll
    for (int ks = 0; ks < 4; ks++) {
        const int ch = ks * 2 + lh;          // 16B k-chunk index (0..7)
        uint32_t af[2][2][4];
#pragma unroll
        for (int arr = 0; arr < 2; arr++)
#pragma unroll
            for (int mi = 0; mi < 2; mi++) {
                int r = wm + mi * 16 + lm;
                ldmx4(af[arr][mi], sA + arr * 16384 + r * 128 + ((ch ^ (r & 7)) << 4));
            }
#pragma unroll
        for (int g = 0; g < 2; g++) {
            uint32_t bfr[4][4];
#pragma unroll
            for (int nb = 0; nb < 4; nb++) {
                int r = wn + nb * 16 + lm;
                ldmx4(bfr[nb], sB + g * 16384 + r * 128 + ((ch ^ (r & 7)) << 4));
            }
#pragma unroll
            for (int a = 0; a < 2; a++) {
                if (a < NApg[g]) {
#pragma unroll
                    for (int mi = 0; mi < 2; mi++)
#pragma unroll
                        for (int nb = 0; nb < 4; nb++) {
                            mma_f16(acc[mi][nb * 2 + 0], af[a][mi], bfr[nb][0], bfr[nb][2]);
                            mma_f16(acc[mi][nb * 2 + 1], af[a][mi], bfr[nb][1], bfr[nb][3]);
                        }
                }
            }
        }
    }

    // ---- direct write of block (bi, bj) ----
    const int rl = wm + (lane >> 2);          // local row (of first mi)
    const int cl = wn + (lane & 3) * 2;       // local col
    const int rowb = bi * 128 + rl;
    const int colb = bj * 128 + cl;
#pragma unroll
    for (int mi = 0; mi < 2; mi++) {
#pragma unroll
        for (int jj = 0; jj < 8; jj++) {
            const float* d = acc[mi][jj];
            size_t o0 = (size_t)(rowb + mi * 16) * 16384ull + colb + jj * 8;
            size_t o1 = o0 + 8ull * 16384ull;
            float2 v0 = make_float2(d[0], d[1]);
            float2 v1 = make_float2(d[2], d[3]);
            __stcs(reinterpret_cast<float2*>(padj + o0), v0);
            __stcs(reinterpret_cast<float2*>(padj + o1), v1);
            float2 m0 = make_float2(v0.x > 0.f ? 1.f : 0.f, v0.y > 0.f ? 1.f : 0.f);
            float2 m1 = make_float2(v1.x > 0.f ? 1.f : 0.f, v1.y > 0.f ? 1.f : 0.f);
            __stcs(reinterpret_cast<float2*>(maskp + o0), m0);
            __stcs(reinterpret_cast<float2*>(maskp + o1), m1);
        }
    }

    // ---- mirrored write of block (bj, bi) via smem transpose ----
    if (bi != bj) {
        __syncthreads();
        float* smt = reinterpret_cast<float*>(smem);
#pragma unroll
        for (int mi = 0; mi < 2; mi++) {
#pragma unroll
            for (int jj = 0; jj < 8; jj++) {
                const float* d = acc[mi][jj];
                int r = rl + mi * 16;
                int c = cl + jj * 8;
                smt[(c + 0) * TSTRIDE + r]     = d[0];
                smt[(c + 1) * TSTRIDE + r]     = d[1];
                smt[(c + 0) * TSTRIDE + r + 8] = d[2];
                smt[(c + 1) * TSTRIDE + r + 8] = d[3];
            }
        }
        __syncthreads();
        // float4 write-out: one warp covers one 512B row segment
        for (int i = tid; i < 4096; i += 256) {
            int r = i >> 5, c4 = (i & 31) * 4;
            float4 v = *reinterpret_cast<const float4*>(smt + r * TSTRIDE + c4);
            size_t o = (size_t)(bj * 128 + r) * 16384ull + (size_t)bi * 128 + c4;
            __stcs(reinterpret_cast<float4*>(padj + o), v);
            float4 mk = make_float4(v.x > 0.f ? 1.f : 0.f, v.y > 0.f ? 1.f : 0.f,
                                    v.z > 0.f ? 1.f : 0.f, v.w > 0.f ? 1.f : 0.f);
            __stcs(reinterpret_cast<float4*>(maskp + o), mk);
        }
    }
}

// ============================================================
extern "C" void kernel_launch(void* const* d_in, const int* in_sizes, int n_in,
                              void* d_out, int out_size) {
    const float* x   = (const float*)d_in[0];
    const int*   ei  = (const int*)d_in[1];
    const int*   elb = (const int*)d_in[2];
    const float* Wl1 = (const float*)d_in[3];
    const float* bl1 = (const float*)d_in[4];
    const float* Wr1 = (const float*)d_in[5];
    const float* Wl2 = (const float*)d_in[6];
    const float* bl2 = (const float*)d_in[7];
    const float* Wr2 = (const float*)d_in[8];

    float* out   = (float*)d_out;
    float* sage1 = out + O_SAGE1;
    float* z     = out + O_Z;
    float* dmul  = out + O_DMUL;
    float* dsum  = out + O_DSUM;
    float* padj  = out + O_PADJ;
    float* maskp = out + O_MASK;

    (void)cudaFuncSetAttribute(k_bigmm_mma, cudaFuncAttributeMaxDynamicSharedMemorySize, SMEM_MM);

    k_zero<<<3088, 256>>>();
    k_scatter1<<<65536, 256>>>(x, ei, ei + N_EDGES);
    k_gemm1<<<256, 256>>>(x, Wl1, Wr1, bl1, sage1);
    k_gemm_pre<<<256, 256>>>(sage1, Wl2);
    k_scatter2<<<32768, 256>>>(ei, ei + N_EDGES);
    k_gemm2<<<256, 256>>>(sage1, Wr2, bl2, z);
    k_decode<<<16384, 256>>>(z, elb, dmul, dsum);
    k_bigmm_mma<<<8256, 256, SMEM_MM>>>(padj, maskp);
}